// round 12
// baseline (speedup 1.0000x reference)
#include <cuda_runtime.h>
#include <cuda_bf16.h>
#include <math.h>
#include <stdint.h>

// ---------------- problem constants ----------------
#define BATCH   2
#define SEQ     2048
#define DMODEL  1024
#define NHEADS  16
#define DHEAD   64
#define MROWS   (BATCH*SEQ)          // 4096
#define SCALE   0.125f

// ---------------- device scratch ----------------
__device__ float g_rc[SEQ * 32];
__device__ float g_rs[SEQ * 32];
__device__ __nv_bfloat16 g_ah[MROWS * DMODEL];       // x hi, later ctx hi
__device__ __nv_bfloat16 g_al[MROWS * DMODEL];       // x lo, later ctx lo
__device__ __nv_bfloat16 g_wth[4 * DMODEL * DMODEL]; // W^T hi, slots q,k,v,o
__device__ __nv_bfloat16 g_wtl[4 * DMODEL * DMODEL]; // W^T lo
__device__ __nv_bfloat16 g_qh[MROWS * DMODEL];
__device__ __nv_bfloat16 g_ql[MROWS * DMODEL];
__device__ __nv_bfloat16 g_kh[MROWS * DMODEL];
__device__ __nv_bfloat16 g_kl[MROWS * DMODEL];
__device__ __nv_bfloat16 g_vh[MROWS * DMODEL];
__device__ __nv_bfloat16 g_vl[MROWS * DMODEL];

// ---------------- PTX helpers (sm_100 base-target safe) ----------------
__device__ __forceinline__ uint32_t smem_u32(const void* p) {
    uint32_t a;
    asm("{ .reg .u64 t; cvta.to.shared.u64 t, %1; cvt.u32.u64 %0, t; }" : "=r"(a) : "l"(p));
    return a;
}
__device__ __forceinline__ void cpasync16(uint32_t sdst, const void* gsrc) {
    asm volatile("cp.async.cg.shared.global [%0], [%1], 16;" :: "r"(sdst), "l"(gsrc));
}
__device__ __forceinline__ void cpasync_commit() {
    asm volatile("cp.async.commit_group;" ::: "memory");
}
__device__ __forceinline__ void ldsm4(uint32_t* d, uint32_t addr) {
    asm volatile("ldmatrix.sync.aligned.m8n8.x4.shared.b16 {%0,%1,%2,%3}, [%4];"
                 : "=r"(d[0]), "=r"(d[1]), "=r"(d[2]), "=r"(d[3]) : "r"(addr));
}
__device__ __forceinline__ void ldsm4t(uint32_t* d, uint32_t addr) {
    asm volatile("ldmatrix.sync.aligned.m8n8.x4.trans.shared.b16 {%0,%1,%2,%3}, [%4];"
                 : "=r"(d[0]), "=r"(d[1]), "=r"(d[2]), "=r"(d[3]) : "r"(addr));
}
__device__ __forceinline__ void mma16816(float* c, const uint32_t* a, const uint32_t* b) {
    asm volatile(
        "mma.sync.aligned.m16n8k16.row.col.f32.bf16.bf16.f32 "
        "{%0,%1,%2,%3}, {%4,%5,%6,%7}, {%8,%9}, {%0,%1,%2,%3};"
        : "+f"(c[0]), "+f"(c[1]), "+f"(c[2]), "+f"(c[3])
        : "r"(a[0]), "r"(a[1]), "r"(a[2]), "r"(a[3]), "r"(b[0]), "r"(b[1]));
}
__device__ __forceinline__ uint32_t swz(uint32_t off) {    // 128B-row swizzle
    return off ^ ((off >> 3) & 0x70);
}
__device__ __forceinline__ uint32_t swz64(uint32_t off) {  // 64B-row swizzle
    return off ^ ((off >> 3) & 0x30);
}

// ---------------- RoPE tables ----------------
__global__ void rope_table_kernel() {
    int t = blockIdx.x, i = threadIdx.x;
    float inv = powf(10000.0f, -(2.0f * (float)i) / 64.0f);
    float ang = (float)t * inv;
    g_rc[t * 32 + i] = cosf(ang);
    g_rs[t * 32 + i] = sinf(ang);
}

// ---------------- fp32 -> bf16 hi/lo split ----------------
__global__ __launch_bounds__(256)
void split_kernel(const float* __restrict__ src,
                  __nv_bfloat16* __restrict__ hi,
                  __nv_bfloat16* __restrict__ lo, int n) {
    int i = (blockIdx.x * 256 + threadIdx.x) * 4;
    if (i >= n) return;
    float4 v = *(const float4*)(src + i);
    float a[4] = {v.x, v.y, v.z, v.w};
    #pragma unroll
    for (int j = 0; j < 4; j++) {
        __nv_bfloat16 h = __float2bfloat16(a[j]);
        hi[i + j] = h;
        lo[i + j] = __float2bfloat16(a[j] - __bfloat162float(h));
    }
}

// ---------------- all four W[K][N] -> W^T hi/lo [N][K] in one launch ----------------
__global__ __launch_bounds__(256)
void tsplit4_kernel(const float* __restrict__ W0, const float* __restrict__ W1,
                    const float* __restrict__ W2, const float* __restrict__ W3) {
    __shared__ float t[32][33];
    int z  = blockIdx.z;
    const float* W = (z == 0) ? W0 : (z == 1) ? W1 : (z == 2) ? W2 : W3;
    size_t slot = (size_t)z * DMODEL * DMODEL;
    int bn = blockIdx.x * 32;
    int bk = blockIdx.y * 32;
    int x = threadIdx.x, y0 = threadIdx.y;   // 32 x 8
    #pragma unroll
    for (int yy = y0; yy < 32; yy += 8)
        t[yy][x] = W[(size_t)(bk + yy) * DMODEL + bn + x];
    __syncthreads();
    #pragma unroll
    for (int yy = y0; yy < 32; yy += 8) {
        float v = t[x][yy];
        __nv_bfloat16 h = __float2bfloat16(v);
        size_t o = slot + (size_t)(bn + yy) * DMODEL + bk + x;
        g_wth[o] = h;
        g_wtl[o] = __float2bfloat16(v - __bfloat162float(h));
    }
}

// ---------------- mma.sync bf16-split GEMM (unchanged from R10) ----------------
#define TILE_B    8192
#define STAGE_B   (4 * TILE_B)            // 32KB
#define SM_GEMM_TOTAL (3 * STAGE_B)       // 98304

template<int FUSED>
__global__ __launch_bounds__(256, 2)
void gemm_big_kernel(const __nv_bfloat16* __restrict__ Ah,
                     const __nv_bfloat16* __restrict__ Al,
                     const float* __restrict__ b0,
                     const float* __restrict__ b1,
                     const float* __restrict__ b2,
                     __nv_bfloat16* __restrict__ o0h, __nv_bfloat16* __restrict__ o0l,
                     __nv_bfloat16* __restrict__ o1h, __nv_bfloat16* __restrict__ o1l,
                     __nv_bfloat16* __restrict__ o2h, __nv_bfloat16* __restrict__ o2l,
                     float* __restrict__ Cf)
{
    extern __shared__ char smem[];
    uint32_t sb = smem_u32(smem);
    int tid  = threadIdx.x;
    int wid  = tid >> 5;
    int lane = tid & 31;
    int row0 = blockIdx.y * 128;
    int col0 = blockIdx.x * 128;
    int z    = FUSED ? blockIdx.z : 3;

    const __nv_bfloat16* srcAh = Ah + (size_t)row0 * DMODEL;
    const __nv_bfloat16* srcAl = Al + (size_t)row0 * DMODEL;
    const __nv_bfloat16* srcBh = g_wth + (size_t)z * DMODEL * DMODEL + (size_t)col0 * DMODEL;
    const __nv_bfloat16* srcBl = g_wtl + (size_t)z * DMODEL * DMODEL + (size_t)col0 * DMODEL;

    int m0w = (wid & 3) * 32;
    int n0w = (wid >> 2) * 64;

    float acc[2][8][4];
    #pragma unroll
    for (int i = 0; i < 2; i++)
        #pragma unroll
        for (int j = 0; j < 8; j++)
            #pragma unroll
            for (int r = 0; r < 4; r++) acc[i][j][r] = 0.f;

    auto prefetch = [&](int s, uint32_t base) {
        int kc = s * 32;
        #pragma unroll
        for (int i = 0; i < 2; i++) {
            int flat = i * 256 + tid;
            int r  = flat >> 2;
            int ch = flat & 3;
            uint32_t sw = swz64((uint32_t)(r * 64 + ch * 16));
            size_t go = (size_t)r * DMODEL + kc + ch * 8;
            cpasync16(base + 0 * TILE_B + sw, srcAh + go);
            cpasync16(base + 1 * TILE_B + sw, srcAl + go);
            cpasync16(base + 2 * TILE_B + sw, srcBh + go);
            cpasync16(base + 3 * TILE_B + sw, srcBl + go);
        }
        cpasync_commit();
    };

    prefetch(0, sb);
    prefetch(1, sb + STAGE_B);

    int raA = (lane & 15);
    int caA = (lane >> 4) * 16;
    int rbB = ((lane >> 4) << 3) + (lane & 7);
    int cbB = ((lane >> 3) & 1) * 16;

    for (int s = 0; s < 32; s++) {
        if (s + 2 < 32) {
            prefetch(s + 2, sb + (uint32_t)((s + 2) % 3) * STAGE_B);
            asm volatile("cp.async.wait_group 2;" ::: "memory");
        } else if (s + 1 < 32) {
            asm volatile("cp.async.wait_group 1;" ::: "memory");
        } else {
            asm volatile("cp.async.wait_group 0;" ::: "memory");
        }
        __syncthreads();

        uint32_t base = sb + (uint32_t)(s % 3) * STAGE_B;
        uint32_t bAh = base;
        uint32_t bAl = base + TILE_B;
        uint32_t bBh = base + 2 * TILE_B;
        uint32_t bBl = base + 3 * TILE_B;

        #pragma unroll
        for (int kk = 0; kk < 2; kk++) {
            int cb = kk * 32;
            uint32_t ah[2][4], al[2][4];
            #pragma unroll
            for (int i = 0; i < 2; i++) {
                uint32_t off = swz64((uint32_t)((m0w + i * 16 + raA) * 64 + cb + caA));
                ldsm4(ah[i], bAh + off);
                ldsm4(al[i], bAl + off);
            }
            #pragma unroll
            for (int jp = 0; jp < 4; jp++) {
                uint32_t bh4[4], bl4[4];
                uint32_t off = swz64((uint32_t)((n0w + jp * 16 + rbB) * 64 + cb + cbB));
                ldsm4(bh4, bBh + off);
                ldsm4(bl4, bBl + off);
                #pragma unroll
                for (int i = 0; i < 2; i++) {
                    #pragma unroll
                    for (int hf = 0; hf < 2; hf++) {
                        int j = jp * 2 + hf;
                        const uint32_t* Bhf = &bh4[hf * 2];
                        const uint32_t* Blf = &bl4[hf * 2];
                        mma16816(acc[i][j], ah[i], Bhf);
                        mma16816(acc[i][j], ah[i], Blf);
                        mma16816(acc[i][j], al[i], Bhf);
                    }
                }
            }
        }
        __syncthreads();
    }

    const float* bias;
    __nv_bfloat16 *Ch, *Cl;
    int applyRope;
    if (FUSED) {
        bias = (z == 0) ? b0 : (z == 1) ? b1 : b2;
        Ch   = (z == 0) ? o0h : (z == 1) ? o1h : o2h;
        Cl   = (z == 0) ? o0l : (z == 1) ? o1l : o2l;
        applyRope = (z < 2);
    } else {
        bias = b0; Ch = nullptr; Cl = nullptr; applyRope = 0;
    }

    #pragma unroll
    for (int i = 0; i < 2; i++) {
        int m_lo = row0 + m0w + i * 16 + (lane >> 2);
        int m_hi = m_lo + 8;
        int s_lo = m_lo & (SEQ - 1);
        int s_hi = m_hi & (SEQ - 1);
        #pragma unroll
        for (int j = 0; j < 8; j++) {
            int n = col0 + n0w + j * 8 + (lane & 3) * 2;
            float bb0 = bias[n], bb1 = bias[n + 1];
            float v0 = acc[i][j][0] + bb0;
            float v1 = acc[i][j][1] + bb1;
            float v2 = acc[i][j][2] + bb0;
            float v3 = acc[i][j][3] + bb1;
            if (applyRope) {
                int pi = (n & 63) >> 1;
                float c0 = g_rc[s_lo * 32 + pi], s0 = g_rs[s_lo * 32 + pi];
                float c1 = g_rc[s_hi * 32 + pi], s1 = g_rs[s_hi * 32 + pi];
                float t0 = v0 * c0 - v1 * s0;
                float t1 = v0 * s0 + v1 * c0;
                float t2 = v2 * c1 - v3 * s1;
                float t3 = v2 * s1 + v3 * c1;
                v0 = t0; v1 = t1; v2 = t2; v3 = t3;
            }
            if (FUSED) {
                __nv_bfloat162 h01 = __floats2bfloat162_rn(v0, v1);
                __nv_bfloat162 l01 = __floats2bfloat162_rn(
                    v0 - __bfloat162float(h01.x), v1 - __bfloat162float(h01.y));
                __nv_bfloat162 h23 = __floats2bfloat162_rn(v2, v3);
                __nv_bfloat162 l23 = __floats2bfloat162_rn(
                    v2 - __bfloat162float(h23.x), v3 - __bfloat162float(h23.y));
                *(__nv_bfloat162*)(Ch + (size_t)m_lo * DMODEL + n) = h01;
                *(__nv_bfloat162*)(Cl + (size_t)m_lo * DMODEL + n) = l01;
                *(__nv_bfloat162*)(Ch + (size_t)m_hi * DMODEL + n) = h23;
                *(__nv_bfloat162*)(Cl + (size_t)m_hi * DMODEL + n) = l23;
            } else {
                *(float2*)(Cf + (size_t)m_lo * DMODEL + n) = make_float2(v0, v1);
                *(float2*)(Cf + (size_t)m_hi * DMODEL + n) = make_float2(v2, v3);
            }
        }
    }
}

// ---------------- flash attention: software-pipelined QK(j+1) || softmax(j)+PV(j) ----------------
// Q (hi/lo) 32KB + 4-deep KV ring (32KB stages) = 160KB smem, 1 CTA/SM.
#define FSQ_H   0
#define FSQ_L   16384
#define FSKV    32768
#define FKV_STAGE 32768
#define SM_FLASH_TOTAL (FSKV + 4 * FKV_STAGE)   // 163840

__global__ __launch_bounds__(256)
void flash_mma_kernel()
{
    extern __shared__ char smem[];
    uint32_t sb = smem_u32(smem);
    int tid  = threadIdx.x;
    int wid  = tid >> 5;
    int lane = tid & 31;
    int iq   = gridDim.x - 1 - blockIdx.x;   // big causal tiles first
    int bh   = blockIdx.y;
    int b    = bh >> 4;
    int h    = bh & 15;

    const size_t hb = (size_t)(b * SEQ) * DMODEL + h * DHEAD;
    const __nv_bfloat16* Qh = g_qh + hb + (size_t)iq * 128 * DMODEL;
    const __nv_bfloat16* Ql = g_ql + hb + (size_t)iq * 128 * DMODEL;

    const int nblocks = (iq + 1) * 2;

    // KV prefetch body (no commit inside)
    auto prefetch_body = [&](int j) {
        uint32_t base = sb + FSKV + (uint32_t)(j & 3) * FKV_STAGE;
        const __nv_bfloat16* kh = g_kh + hb + (size_t)j * 64 * DMODEL;
        const __nv_bfloat16* kl = g_kl + hb + (size_t)j * 64 * DMODEL;
        const __nv_bfloat16* vh = g_vh + hb + (size_t)j * 64 * DMODEL;
        const __nv_bfloat16* vl = g_vl + hb + (size_t)j * 64 * DMODEL;
        #pragma unroll
        for (int i = 0; i < 2; i++) {
            int flat = i * 256 + tid;
            int r  = flat >> 3;
            int ch = flat & 7;
            uint32_t sw = swz((uint32_t)(r * 128 + ch * 16));
            size_t go = (size_t)r * DMODEL + ch * 8;
            cpasync16(base + 0     + sw, kh + go);
            cpasync16(base + 8192  + sw, kl + go);
            cpasync16(base + 16384 + sw, vh + go);
            cpasync16(base + 24576 + sw, vl + go);
        }
    };

    // prologue: Q joins group 0; always commit 3 groups (uniform accounting)
    #pragma unroll
    for (int i = 0; i < 4; i++) {
        int flat = i * 256 + tid;
        int r  = flat >> 3;
        int ch = flat & 7;
        uint32_t sw = swz((uint32_t)(r * 128 + ch * 16));
        size_t go = (size_t)r * DMODEL + ch * 8;
        cpasync16(sb + FSQ_H + sw, Qh + go);
        cpasync16(sb + FSQ_L + sw, Ql + go);
    }
    prefetch_body(0);
    cpasync_commit();                               // group: Q + kv0
    if (1 < nblocks) prefetch_body(1);
    cpasync_commit();                               // group: kv1 (maybe empty)
    if (2 < nblocks) prefetch_body(2);
    cpasync_commit();                               // group: kv2 (maybe empty)

    const int q0 = wid * 16;
    int raA = (lane & 15);
    int caA = (lane >> 4) * 16;
    int rbB = ((lane >> 4) << 3) + (lane & 7);
    int cbB = ((lane >> 3) & 1) * 16;
    int vrow = lane & 15;
    int vcol = (lane >> 4) * 16;

    const int grow0 = iq * 128 + q0 + (lane >> 2);
    const int grow1 = grow0 + 8;

    float o[8][4];
    #pragma unroll
    for (int j = 0; j < 8; j++)
        #pragma unroll
        for (int r = 0; r < 4; r++) o[j][r] = 0.f;
    float m0 = -1e30f, m1 = -1e30f, l0 = 0.f, l1 = 0.f;

    uint32_t qfh[4][4], qfl[4][4];
    float sbuf[2][8][4];

    // QK of block j into s (raw, unscaled, unmasked)
    auto qk_compute = [&](int j, float (*s)[4]) {
        uint32_t kvb = sb + FSKV + (uint32_t)(j & 3) * FKV_STAGE;
        #pragma unroll
        for (int nt = 0; nt < 8; nt++)
            #pragma unroll
            for (int r = 0; r < 4; r++) s[nt][r] = 0.f;
        #pragma unroll
        for (int kk = 0; kk < 4; kk++) {
            #pragma unroll
            for (int jp = 0; jp < 4; jp++) {
                uint32_t kh4[4], kl4[4];
                uint32_t off = swz((uint32_t)((jp * 16 + rbB) * 128 + kk * 32 + cbB));
                ldsm4(kh4, kvb + 0    + off);
                ldsm4(kl4, kvb + 8192 + off);
                #pragma unroll
                for (int hf = 0; hf < 2; hf++) {
                    int nt = jp * 2 + hf;
                    const uint32_t* Bh_ = &kh4[hf * 2];
                    const uint32_t* Bl_ = &kl4[hf * 2];
                    mma16816(s[nt], qfh[kk], Bh_);
                    mma16816(s[nt], qfh[kk], Bl_);
                    mma16816(s[nt], qfl[kk], Bh_);
                }
            }
        }
    };

    // wait for group 0 (Q + kv0): <=2 groups pending
    asm volatile("cp.async.wait_group 2;" ::: "memory");
    __syncthreads();

    // load Q fragments once
    #pragma unroll
    for (int kk = 0; kk < 4; kk++) {
        uint32_t off = swz((uint32_t)((q0 + raA) * 128 + kk * 32 + caA));
        ldsm4(qfh[kk], sb + FSQ_H + off);
        ldsm4(qfl[kk], sb + FSQ_L + off);
    }
    // QK(0)
    qk_compute(0, sbuf[0]);

    for (int jb = 0; jb < nblocks; jb++) {
        int cur = jb & 1;
        // ensure kv(jb+1) landed (K for next QK; V(jb) already guaranteed earlier)
        if (jb + 1 < nblocks) {
            asm volatile("cp.async.wait_group 1;" ::: "memory");
        } else {
            asm volatile("cp.async.wait_group 0;" ::: "memory");
        }
        __syncthreads();

        // pipelined: issue next block's QK mmas first (tensor pipe busy while
        // softmax below runs on ALU/MUFU)
        if (jb + 1 < nblocks) qk_compute(jb + 1, sbuf[cur ^ 1]);

        float (*s)[4] = sbuf[cur];

        // ---- scale + causal mask for block jb ----
        int kv0 = jb * 64;
        #pragma unroll
        for (int nt = 0; nt < 8; nt++)
            #pragma unroll
            for (int r = 0; r < 4; r++) s[nt][r] *= SCALE;
        if (kv0 + 63 > grow0) {
            #pragma unroll
            for (int nt = 0; nt < 8; nt++) {
                int c = kv0 + nt * 8 + (lane & 3) * 2;
                if (c > grow0)     s[nt][0] = -1e30f;
                if (c + 1 > grow0) s[nt][1] = -1e30f;
                if (c > grow1)     s[nt][2] = -1e30f;
                if (c + 1 > grow1) s[nt][3] = -1e30f;
            }
        }

        // ---- online softmax (exp written in place into s) ----
        float mxa = -1e30f, mxb = -1e30f;
        #pragma unroll
        for (int nt = 0; nt < 8; nt++) {
            mxa = fmaxf(mxa, fmaxf(s[nt][0], s[nt][1]));
            mxb = fmaxf(mxb, fmaxf(s[nt][2], s[nt][3]));
        }
        mxa = fmaxf(mxa, __shfl_xor_sync(0xffffffff, mxa, 1));
        mxa = fmaxf(mxa, __shfl_xor_sync(0xffffffff, mxa, 2));
        mxb = fmaxf(mxb, __shfl_xor_sync(0xffffffff, mxb, 1));
        mxb = fmaxf(mxb, __shfl_xor_sync(0xffffffff, mxb, 2));
        float mn0 = fmaxf(m0, mxa);
        float mn1 = fmaxf(m1, mxb);
        float al0 = __expf(m0 - mn0);
        float al1 = __expf(m1 - mn1);
        m0 = mn0; m1 = mn1;

        float sum0 = 0.f, sum1 = 0.f;
        #pragma unroll
        for (int nt = 0; nt < 8; nt++) {
            s[nt][0] = __expf(s[nt][0] - mn0);
            s[nt][1] = __expf(s[nt][1] - mn0);
            s[nt][2] = __expf(s[nt][2] - mn1);
            s[nt][3] = __expf(s[nt][3] - mn1);
            sum0 += s[nt][0] + s[nt][1];
            sum1 += s[nt][2] + s[nt][3];
        }
        sum0 += __shfl_xor_sync(0xffffffff, sum0, 1);
        sum0 += __shfl_xor_sync(0xffffffff, sum0, 2);
        sum1 += __shfl_xor_sync(0xffffffff, sum1, 1);
        sum1 += __shfl_xor_sync(0xffffffff, sum1, 2);
        l0 = l0 * al0 + sum0;
        l1 = l1 * al1 + sum1;

        #pragma unroll
        for (int nt = 0; nt < 8; nt++) {
            o[nt][0] *= al0; o[nt][1] *= al0;
            o[nt][2] *= al1; o[nt][3] *= al1;
        }

        // ---- pack P (from s) into A-frags, hi/lo ----
        uint32_t pfh[4][4], pfl[4][4];
        #pragma unroll
        for (int t = 0; t < 4; t++) {
            int n0 = 2 * t, n1 = 2 * t + 1;
            float e[8] = {s[n0][0], s[n0][1], s[n0][2], s[n0][3],
                          s[n1][0], s[n1][1], s[n1][2], s[n1][3]};
            #pragma unroll
            for (int g = 0; g < 4; g++) {
                __nv_bfloat162 hh = __floats2bfloat162_rn(e[2*g], e[2*g+1]);
                pfh[t][g] = *(uint32_t*)&hh;
                __nv_bfloat162 ll = __floats2bfloat162_rn(
                    e[2*g]   - __bfloat162float(hh.x),
                    e[2*g+1] - __bfloat162float(hh.y));
                pfl[t][g] = *(uint32_t*)&ll;
            }
        }

        // ---- O += P @ V ----
        {
            uint32_t kvb = sb + FSKV + (uint32_t)(jb & 3) * FKV_STAGE;
            #pragma unroll
            for (int t = 0; t < 4; t++) {
                #pragma unroll
                for (int jp = 0; jp < 4; jp++) {
                    uint32_t vh4[4], vl4[4];
                    uint32_t off = swz((uint32_t)((t * 16 + vrow) * 128 + jp * 32 + vcol));
                    ldsm4t(vh4, kvb + 16384 + off);
                    ldsm4t(vl4, kvb + 24576 + off);
                    #pragma unroll
                    for (int hf = 0; hf < 2; hf++) {
                        int nt = jp * 2 + hf;
                        const uint32_t* Bh_ = &vh4[hf * 2];
                        const uint32_t* Bl_ = &vl4[hf * 2];
                        mma16816(o[nt], pfh[t], Bh_);
                        mma16816(o[nt], pfl[t], Bh_);
                        mma16816(o[nt], pfh[t], Bl_);
                    }
                }
            }
        }

        // prefetch kv(jb+3) into buf (jb+3)&3 — not read this iteration
        // (reads were (jb)&3 and (jb+1)&3), so no trailing barrier needed.
        if (jb + 3 < nblocks) prefetch_body(jb + 3);
        cpasync_commit();   // unconditional: keeps group accounting uniform
    }

    // ---- finalize: normalize, write ctx hi/lo into g_ah/g_al ----
    float inv0 = 1.f / l0;
    float inv1 = 1.f / l1;
    size_t r0g = (size_t)(b * SEQ + grow0) * DMODEL + h * DHEAD;
    size_t r1g = (size_t)(b * SEQ + grow1) * DMODEL + h * DHEAD;
    #pragma unroll
    for (int nt = 0; nt < 8; nt++) {
        int c = nt * 8 + (lane & 3) * 2;
        float v0 = o[nt][0] * inv0, v1 = o[nt][1] * inv0;
        float v2 = o[nt][2] * inv1, v3 = o[nt][3] * inv1;
        __nv_bfloat162 h01 = __floats2bfloat162_rn(v0, v1);
        __nv_bfloat162 l01 = __floats2bfloat162_rn(
            v0 - __bfloat162float(h01.x), v1 - __bfloat162float(h01.y));
        __nv_bfloat162 h23 = __floats2bfloat162_rn(v2, v3);
        __nv_bfloat162 l23 = __floats2bfloat162_rn(
            v2 - __bfloat162float(h23.x), v3 - __bfloat162float(h23.y));
        *(__nv_bfloat162*)(g_ah + r0g + c) = h01;
        *(__nv_bfloat162*)(g_al + r0g + c) = l01;
        *(__nv_bfloat162*)(g_ah + r1g + c) = h23;
        *(__nv_bfloat162*)(g_al + r1g + c) = l23;
    }
}

// ---------------- launch ----------------
extern "C" void kernel_launch(void* const* d_in, const int* in_sizes, int n_in,
                              void* d_out, int out_size)
{
    const float* x  = (const float*)d_in[0];
    const float* Wq = (const float*)d_in[1];
    const float* bq = (const float*)d_in[2];
    const float* Wk = (const float*)d_in[3];
    const float* bk = (const float*)d_in[4];
    const float* Wv = (const float*)d_in[5];
    const float* bv = (const float*)d_in[6];
    const float* Wo = (const float*)d_in[7];
    const float* bo = (const float*)d_in[8];
    float* out = (float*)d_out;

    __nv_bfloat16 *pah, *pal, *pqh, *pql, *pkh, *pkl, *pvh, *pvl;
    cudaGetSymbolAddress((void**)&pah, g_ah);
    cudaGetSymbolAddress((void**)&pal, g_al);
    cudaGetSymbolAddress((void**)&pqh, g_qh);
    cudaGetSymbolAddress((void**)&pql, g_ql);
    cudaGetSymbolAddress((void**)&pkh, g_kh);
    cudaGetSymbolAddress((void**)&pkl, g_kl);
    cudaGetSymbolAddress((void**)&pvh, g_vh);
    cudaGetSymbolAddress((void**)&pvl, g_vl);

    cudaFuncSetAttribute(gemm_big_kernel<1>,
                         cudaFuncAttributeMaxDynamicSharedMemorySize, SM_GEMM_TOTAL);
    cudaFuncSetAttribute(gemm_big_kernel<0>,
                         cudaFuncAttributeMaxDynamicSharedMemorySize, SM_GEMM_TOTAL);
    cudaFuncSetAttribute(flash_mma_kernel,
                         cudaFuncAttributeMaxDynamicSharedMemorySize, SM_FLASH_TOTAL);

    const int nA = MROWS * DMODEL;

    rope_table_kernel<<<SEQ, 32>>>();
    split_kernel<<<nA / 1024, 256>>>(x, pah, pal, nA);
    tsplit4_kernel<<<dim3(32, 32, 4), dim3(32, 8)>>>(Wq, Wk, Wv, Wo);

    // fused Q,K,V projections (2 CTAs/SM, 3-stage pipeline)
    gemm_big_kernel<1><<<dim3(8, 32, 3), 256, SM_GEMM_TOTAL>>>(
        pah, pal, bq, bk, bv,
        pqh, pql, pkh, pkl, pvh, pvl, nullptr);

    // attention (software-pipelined; writes ctx hi/lo into g_ah/g_al)
    flash_mma_kernel<<<dim3(SEQ / 128, BATCH * NHEADS), 256, SM_FLASH_TOTAL>>>();

    // O projection (weight slot 3, fp32 out)
    gemm_big_kernel<0><<<dim3(8, 32, 1), 256, SM_GEMM_TOTAL>>>(
        pah, pal, bo, nullptr, nullptr,
        nullptr, nullptr, nullptr, nullptr, nullptr, nullptr, out);
}

// round 14
// speedup vs baseline: 1.2005x; 1.2005x over previous
#include <cuda_runtime.h>
#include <cuda_bf16.h>
#include <math.h>
#include <stdint.h>

// ---------------- problem constants ----------------
#define BATCH   2
#define SEQ     2048
#define DMODEL  1024
#define NHEADS  16
#define DHEAD   64
#define MROWS   (BATCH*SEQ)          // 4096
#define SCALE   0.125f

// ---------------- device scratch ----------------
__device__ float g_rc[SEQ * 32];
__device__ float g_rs[SEQ * 32];
__device__ __nv_bfloat16 g_ah[MROWS * DMODEL];       // x hi, later ctx hi
__device__ __nv_bfloat16 g_al[MROWS * DMODEL];       // x lo, later ctx lo
__device__ __nv_bfloat16 g_wth[4 * DMODEL * DMODEL]; // W^T hi, slots q,k,v,o
__device__ __nv_bfloat16 g_wtl[4 * DMODEL * DMODEL]; // W^T lo
__device__ __nv_bfloat16 g_qh[MROWS * DMODEL];
__device__ __nv_bfloat16 g_ql[MROWS * DMODEL];
__device__ __nv_bfloat16 g_kh[MROWS * DMODEL];
__device__ __nv_bfloat16 g_kl[MROWS * DMODEL];
__device__ __nv_bfloat16 g_vh[MROWS * DMODEL];
__device__ __nv_bfloat16 g_vl[MROWS * DMODEL];

// ---------------- PTX helpers (sm_100 base-target safe) ----------------
__device__ __forceinline__ uint32_t smem_u32(const void* p) {
    uint32_t a;
    asm("{ .reg .u64 t; cvta.to.shared.u64 t, %1; cvt.u32.u64 %0, t; }" : "=r"(a) : "l"(p));
    return a;
}
__device__ __forceinline__ void cpasync16(uint32_t sdst, const void* gsrc) {
    asm volatile("cp.async.cg.shared.global [%0], [%1], 16;" :: "r"(sdst), "l"(gsrc));
}
__device__ __forceinline__ void cpasync_commit() {
    asm volatile("cp.async.commit_group;" ::: "memory");
}
__device__ __forceinline__ void ldsm4(uint32_t* d, uint32_t addr) {
    asm volatile("ldmatrix.sync.aligned.m8n8.x4.shared.b16 {%0,%1,%2,%3}, [%4];"
                 : "=r"(d[0]), "=r"(d[1]), "=r"(d[2]), "=r"(d[3]) : "r"(addr));
}
__device__ __forceinline__ void ldsm4t(uint32_t* d, uint32_t addr) {
    asm volatile("ldmatrix.sync.aligned.m8n8.x4.trans.shared.b16 {%0,%1,%2,%3}, [%4];"
                 : "=r"(d[0]), "=r"(d[1]), "=r"(d[2]), "=r"(d[3]) : "r"(addr));
}
__device__ __forceinline__ void mma16816(float* c, const uint32_t* a, const uint32_t* b) {
    asm volatile(
        "mma.sync.aligned.m16n8k16.row.col.f32.bf16.bf16.f32 "
        "{%0,%1,%2,%3}, {%4,%5,%6,%7}, {%8,%9}, {%0,%1,%2,%3};"
        : "+f"(c[0]), "+f"(c[1]), "+f"(c[2]), "+f"(c[3])
        : "r"(a[0]), "r"(a[1]), "r"(a[2]), "r"(a[3]), "r"(b[0]), "r"(b[1]));
}
__device__ __forceinline__ uint32_t swz(uint32_t off) {    // 128B-row swizzle
    return off ^ ((off >> 3) & 0x70);
}
__device__ __forceinline__ uint32_t swz64(uint32_t off) {  // 64B-row swizzle
    return off ^ ((off >> 3) & 0x30);
}

// ---------------- RoPE tables ----------------
__global__ void rope_table_kernel() {
    int t = blockIdx.x, i = threadIdx.x;
    float inv = powf(10000.0f, -(2.0f * (float)i) / 64.0f);
    float ang = (float)t * inv;
    g_rc[t * 32 + i] = cosf(ang);
    g_rs[t * 32 + i] = sinf(ang);
}

// ---------------- fp32 -> bf16 hi/lo split ----------------
__global__ __launch_bounds__(256)
void split_kernel(const float* __restrict__ src,
                  __nv_bfloat16* __restrict__ hi,
                  __nv_bfloat16* __restrict__ lo, int n) {
    int i = (blockIdx.x * 256 + threadIdx.x) * 4;
    if (i >= n) return;
    float4 v = *(const float4*)(src + i);
    float a[4] = {v.x, v.y, v.z, v.w};
    #pragma unroll
    for (int j = 0; j < 4; j++) {
        __nv_bfloat16 h = __float2bfloat16(a[j]);
        hi[i + j] = h;
        lo[i + j] = __float2bfloat16(a[j] - __bfloat162float(h));
    }
}

// ---------------- all four W[K][N] -> W^T hi/lo [N][K] in one launch ----------------
__global__ __launch_bounds__(256)
void tsplit4_kernel(const float* __restrict__ W0, const float* __restrict__ W1,
                    const float* __restrict__ W2, const float* __restrict__ W3) {
    __shared__ float t[32][33];
    int z  = blockIdx.z;
    const float* W = (z == 0) ? W0 : (z == 1) ? W1 : (z == 2) ? W2 : W3;
    size_t slot = (size_t)z * DMODEL * DMODEL;
    int bn = blockIdx.x * 32;
    int bk = blockIdx.y * 32;
    int x = threadIdx.x, y0 = threadIdx.y;   // 32 x 8
    #pragma unroll
    for (int yy = y0; yy < 32; yy += 8)
        t[yy][x] = W[(size_t)(bk + yy) * DMODEL + bn + x];
    __syncthreads();
    #pragma unroll
    for (int yy = y0; yy < 32; yy += 8) {
        float v = t[x][yy];
        __nv_bfloat16 h = __float2bfloat16(v);
        size_t o = slot + (size_t)(bn + yy) * DMODEL + bk + x;
        g_wth[o] = h;
        g_wtl[o] = __float2bfloat16(v - __bfloat162float(h));
    }
}

// ---------------- mma.sync bf16-split GEMM (unchanged from R10) ----------------
#define TILE_B    8192
#define STAGE_B   (4 * TILE_B)            // 32KB
#define SM_GEMM_TOTAL (3 * STAGE_B)       // 98304

template<int FUSED>
__global__ __launch_bounds__(256, 2)
void gemm_big_kernel(const __nv_bfloat16* __restrict__ Ah,
                     const __nv_bfloat16* __restrict__ Al,
                     const float* __restrict__ b0,
                     const float* __restrict__ b1,
                     const float* __restrict__ b2,
                     __nv_bfloat16* __restrict__ o0h, __nv_bfloat16* __restrict__ o0l,
                     __nv_bfloat16* __restrict__ o1h, __nv_bfloat16* __restrict__ o1l,
                     __nv_bfloat16* __restrict__ o2h, __nv_bfloat16* __restrict__ o2l,
                     float* __restrict__ Cf)
{
    extern __shared__ char smem[];
    uint32_t sb = smem_u32(smem);
    int tid  = threadIdx.x;
    int wid  = tid >> 5;
    int lane = tid & 31;
    int row0 = blockIdx.y * 128;
    int col0 = blockIdx.x * 128;
    int z    = FUSED ? blockIdx.z : 3;

    const __nv_bfloat16* srcAh = Ah + (size_t)row0 * DMODEL;
    const __nv_bfloat16* srcAl = Al + (size_t)row0 * DMODEL;
    const __nv_bfloat16* srcBh = g_wth + (size_t)z * DMODEL * DMODEL + (size_t)col0 * DMODEL;
    const __nv_bfloat16* srcBl = g_wtl + (size_t)z * DMODEL * DMODEL + (size_t)col0 * DMODEL;

    int m0w = (wid & 3) * 32;
    int n0w = (wid >> 2) * 64;

    float acc[2][8][4];
    #pragma unroll
    for (int i = 0; i < 2; i++)
        #pragma unroll
        for (int j = 0; j < 8; j++)
            #pragma unroll
            for (int r = 0; r < 4; r++) acc[i][j][r] = 0.f;

    auto prefetch = [&](int s, uint32_t base) {
        int kc = s * 32;
        #pragma unroll
        for (int i = 0; i < 2; i++) {
            int flat = i * 256 + tid;
            int r  = flat >> 2;
            int ch = flat & 3;
            uint32_t sw = swz64((uint32_t)(r * 64 + ch * 16));
            size_t go = (size_t)r * DMODEL + kc + ch * 8;
            cpasync16(base + 0 * TILE_B + sw, srcAh + go);
            cpasync16(base + 1 * TILE_B + sw, srcAl + go);
            cpasync16(base + 2 * TILE_B + sw, srcBh + go);
            cpasync16(base + 3 * TILE_B + sw, srcBl + go);
        }
        cpasync_commit();
    };

    prefetch(0, sb);
    prefetch(1, sb + STAGE_B);

    int raA = (lane & 15);
    int caA = (lane >> 4) * 16;
    int rbB = ((lane >> 4) << 3) + (lane & 7);
    int cbB = ((lane >> 3) & 1) * 16;

    for (int s = 0; s < 32; s++) {
        if (s + 2 < 32) {
            prefetch(s + 2, sb + (uint32_t)((s + 2) % 3) * STAGE_B);
            asm volatile("cp.async.wait_group 2;" ::: "memory");
        } else if (s + 1 < 32) {
            asm volatile("cp.async.wait_group 1;" ::: "memory");
        } else {
            asm volatile("cp.async.wait_group 0;" ::: "memory");
        }
        __syncthreads();

        uint32_t base = sb + (uint32_t)(s % 3) * STAGE_B;
        uint32_t bAh = base;
        uint32_t bAl = base + TILE_B;
        uint32_t bBh = base + 2 * TILE_B;
        uint32_t bBl = base + 3 * TILE_B;

        #pragma unroll
        for (int kk = 0; kk < 2; kk++) {
            int cb = kk * 32;
            uint32_t ah[2][4], al[2][4];
            #pragma unroll
            for (int i = 0; i < 2; i++) {
                uint32_t off = swz64((uint32_t)((m0w + i * 16 + raA) * 64 + cb + caA));
                ldsm4(ah[i], bAh + off);
                ldsm4(al[i], bAl + off);
            }
            #pragma unroll
            for (int jp = 0; jp < 4; jp++) {
                uint32_t bh4[4], bl4[4];
                uint32_t off = swz64((uint32_t)((n0w + jp * 16 + rbB) * 64 + cb + cbB));
                ldsm4(bh4, bBh + off);
                ldsm4(bl4, bBl + off);
                #pragma unroll
                for (int i = 0; i < 2; i++) {
                    #pragma unroll
                    for (int hf = 0; hf < 2; hf++) {
                        int j = jp * 2 + hf;
                        const uint32_t* Bhf = &bh4[hf * 2];
                        const uint32_t* Blf = &bl4[hf * 2];
                        mma16816(acc[i][j], ah[i], Bhf);
                        mma16816(acc[i][j], ah[i], Blf);
                        mma16816(acc[i][j], al[i], Bhf);
                    }
                }
            }
        }
        __syncthreads();
    }

    const float* bias;
    __nv_bfloat16 *Ch, *Cl;
    int applyRope;
    if (FUSED) {
        bias = (z == 0) ? b0 : (z == 1) ? b1 : b2;
        Ch   = (z == 0) ? o0h : (z == 1) ? o1h : o2h;
        Cl   = (z == 0) ? o0l : (z == 1) ? o1l : o2l;
        applyRope = (z < 2);
    } else {
        bias = b0; Ch = nullptr; Cl = nullptr; applyRope = 0;
    }

    #pragma unroll
    for (int i = 0; i < 2; i++) {
        int m_lo = row0 + m0w + i * 16 + (lane >> 2);
        int m_hi = m_lo + 8;
        int s_lo = m_lo & (SEQ - 1);
        int s_hi = m_hi & (SEQ - 1);
        #pragma unroll
        for (int j = 0; j < 8; j++) {
            int n = col0 + n0w + j * 8 + (lane & 3) * 2;
            float bb0 = bias[n], bb1 = bias[n + 1];
            float v0 = acc[i][j][0] + bb0;
            float v1 = acc[i][j][1] + bb1;
            float v2 = acc[i][j][2] + bb0;
            float v3 = acc[i][j][3] + bb1;
            if (applyRope) {
                int pi = (n & 63) >> 1;
                float c0 = g_rc[s_lo * 32 + pi], s0 = g_rs[s_lo * 32 + pi];
                float c1 = g_rc[s_hi * 32 + pi], s1 = g_rs[s_hi * 32 + pi];
                float t0 = v0 * c0 - v1 * s0;
                float t1 = v0 * s0 + v1 * c0;
                float t2 = v2 * c1 - v3 * s1;
                float t3 = v2 * s1 + v3 * c1;
                v0 = t0; v1 = t1; v2 = t2; v3 = t3;
            }
            if (FUSED) {
                __nv_bfloat162 h01 = __floats2bfloat162_rn(v0, v1);
                __nv_bfloat162 l01 = __floats2bfloat162_rn(
                    v0 - __bfloat162float(h01.x), v1 - __bfloat162float(h01.y));
                __nv_bfloat162 h23 = __floats2bfloat162_rn(v2, v3);
                __nv_bfloat162 l23 = __floats2bfloat162_rn(
                    v2 - __bfloat162float(h23.x), v3 - __bfloat162float(h23.y));
                *(__nv_bfloat162*)(Ch + (size_t)m_lo * DMODEL + n) = h01;
                *(__nv_bfloat162*)(Cl + (size_t)m_lo * DMODEL + n) = l01;
                *(__nv_bfloat162*)(Ch + (size_t)m_hi * DMODEL + n) = h23;
                *(__nv_bfloat162*)(Cl + (size_t)m_hi * DMODEL + n) = l23;
            } else {
                *(float2*)(Cf + (size_t)m_lo * DMODEL + n) = make_float2(v0, v1);
                *(float2*)(Cf + (size_t)m_hi * DMODEL + n) = make_float2(v2, v3);
            }
        }
    }
}

// ---------------- flash attention: 64 q-rows / 128 threads / 2 CTAs per SM ----------------
// Q (hi/lo) 16KB + 2-deep KV ring (32KB stages) = 80KB smem -> 2 CTAs/SM.
// Inner math identical to the R10 (546.8us) version; only the CTA shape changed.
#define FSQ_H   0
#define FSQ_L   8192
#define FSKV    16384
#define FKV_STAGE 32768
#define SM_FLASH_TOTAL (FSKV + 2 * FKV_STAGE)   // 81920

__global__ __launch_bounds__(128)
void flash_mma_kernel()
{
    extern __shared__ char smem[];
    uint32_t sb = smem_u32(smem);
    int tid  = threadIdx.x;
    int wid  = tid >> 5;          // 0..3
    int lane = tid & 31;
    int iq   = gridDim.x - 1 - blockIdx.x;   // big causal tiles first
    int bh   = blockIdx.y;
    int b    = bh >> 4;
    int h    = bh & 15;

    const size_t hb = (size_t)(b * SEQ) * DMODEL + h * DHEAD;
    const __nv_bfloat16* Qh = g_qh + hb + (size_t)iq * 64 * DMODEL;
    const __nv_bfloat16* Ql = g_ql + hb + (size_t)iq * 64 * DMODEL;

    // Q load (64 rows x 128B per split): 512 chunks each, 128 threads x 4
    #pragma unroll
    for (int i = 0; i < 4; i++) {
        int flat = i * 128 + tid;
        int r  = flat >> 3;
        int ch = flat & 7;
        uint32_t sw = swz((uint32_t)(r * 128 + ch * 16));
        size_t go = (size_t)r * DMODEL + ch * 8;
        cpasync16(sb + FSQ_H + sw, Qh + go);
        cpasync16(sb + FSQ_L + sw, Ql + go);
    }

    auto prefetch_kv = [&](int j) {
        uint32_t base = sb + FSKV + (uint32_t)(j & 1) * FKV_STAGE;
        const __nv_bfloat16* kh = g_kh + hb + (size_t)j * 64 * DMODEL;
        const __nv_bfloat16* kl = g_kl + hb + (size_t)j * 64 * DMODEL;
        const __nv_bfloat16* vh = g_vh + hb + (size_t)j * 64 * DMODEL;
        const __nv_bfloat16* vl = g_vl + hb + (size_t)j * 64 * DMODEL;
        #pragma unroll
        for (int i = 0; i < 4; i++) {
            int flat = i * 128 + tid;
            int r  = flat >> 3;
            int ch = flat & 7;
            uint32_t sw = swz((uint32_t)(r * 128 + ch * 16));
            size_t go = (size_t)r * DMODEL + ch * 8;
            cpasync16(base + 0     + sw, kh + go);
            cpasync16(base + 8192  + sw, kl + go);
            cpasync16(base + 16384 + sw, vh + go);
            cpasync16(base + 24576 + sw, vl + go);
        }
        cpasync_commit();
    };

    prefetch_kv(0);   // group 0 includes Q

    const int nblocks = iq + 1;   // 64-row q tile: causal needs kv blocks 0..iq
    const int q0 = wid * 16;

    int raA = (lane & 15);
    int caA = (lane >> 4) * 16;
    int rbB = ((lane >> 4) << 3) + (lane & 7);
    int cbB = ((lane >> 3) & 1) * 16;
    int vrow = lane & 15;
    int vcol = (lane >> 4) * 16;

    const int grow0 = iq * 64 + q0 + (lane >> 2);
    const int grow1 = grow0 + 8;

    float o[8][4];
    #pragma unroll
    for (int j = 0; j < 8; j++)
        #pragma unroll
        for (int r = 0; r < 4; r++) o[j][r] = 0.f;
    float m0 = -1e30f, m1 = -1e30f, l0 = 0.f, l1 = 0.f;

    uint32_t qfh[4][4], qfl[4][4];
    bool qloaded = false;

    for (int jb = 0; jb < nblocks; jb++) {
        if (jb + 1 < nblocks) {
            prefetch_kv(jb + 1);
            asm volatile("cp.async.wait_group 1;" ::: "memory");
        } else {
            asm volatile("cp.async.wait_group 0;" ::: "memory");
        }
        __syncthreads();

        if (!qloaded) {
            #pragma unroll
            for (int kk = 0; kk < 4; kk++) {
                uint32_t off = swz((uint32_t)((q0 + raA) * 128 + kk * 32 + caA));
                ldsm4(qfh[kk], sb + FSQ_H + off);
                ldsm4(qfl[kk], sb + FSQ_L + off);
            }
            qloaded = true;
        }

        uint32_t kvb = sb + FSKV + (uint32_t)(jb & 1) * FKV_STAGE;

        float s[8][4];
        #pragma unroll
        for (int j = 0; j < 8; j++)
            #pragma unroll
            for (int r = 0; r < 4; r++) s[j][r] = 0.f;

        #pragma unroll
        for (int kk = 0; kk < 4; kk++) {
            #pragma unroll
            for (int jp = 0; jp < 4; jp++) {
                uint32_t kh4[4], kl4[4];
                uint32_t off = swz((uint32_t)((jp * 16 + rbB) * 128 + kk * 32 + cbB));
                ldsm4(kh4, kvb + 0    + off);
                ldsm4(kl4, kvb + 8192 + off);
                #pragma unroll
                for (int hf = 0; hf < 2; hf++) {
                    int nt = jp * 2 + hf;
                    const uint32_t* Bh_ = &kh4[hf * 2];
                    const uint32_t* Bl_ = &kl4[hf * 2];
                    mma16816(s[nt], qfh[kk], Bh_);
                    mma16816(s[nt], qfh[kk], Bl_);
                    mma16816(s[nt], qfl[kk], Bh_);
                }
            }
        }

        int kv0 = jb * 64;
        #pragma unroll
        for (int nt = 0; nt < 8; nt++)
            #pragma unroll
            for (int r = 0; r < 4; r++) s[nt][r] *= SCALE;
        if (kv0 + 63 > grow0) {
            #pragma unroll
            for (int nt = 0; nt < 8; nt++) {
                int c = kv0 + nt * 8 + (lane & 3) * 2;
                if (c > grow0)     s[nt][0] = -1e30f;
                if (c + 1 > grow0) s[nt][1] = -1e30f;
                if (c > grow1)     s[nt][2] = -1e30f;
                if (c + 1 > grow1) s[nt][3] = -1e30f;
            }
        }

        float mxa = -1e30f, mxb = -1e30f;
        #pragma unroll
        for (int nt = 0; nt < 8; nt++) {
            mxa = fmaxf(mxa, fmaxf(s[nt][0], s[nt][1]));
            mxb = fmaxf(mxb, fmaxf(s[nt][2], s[nt][3]));
        }
        mxa = fmaxf(mxa, __shfl_xor_sync(0xffffffff, mxa, 1));
        mxa = fmaxf(mxa, __shfl_xor_sync(0xffffffff, mxa, 2));
        mxb = fmaxf(mxb, __shfl_xor_sync(0xffffffff, mxb, 1));
        mxb = fmaxf(mxb, __shfl_xor_sync(0xffffffff, mxb, 2));
        float mn0 = fmaxf(m0, mxa);
        float mn1 = fmaxf(m1, mxb);
        float al0 = __expf(m0 - mn0);
        float al1 = __expf(m1 - mn1);
        m0 = mn0; m1 = mn1;

        float p[8][4];
        float sum0 = 0.f, sum1 = 0.f;
        #pragma unroll
        for (int nt = 0; nt < 8; nt++) {
            p[nt][0] = __expf(s[nt][0] - mn0);
            p[nt][1] = __expf(s[nt][1] - mn0);
            p[nt][2] = __expf(s[nt][2] - mn1);
            p[nt][3] = __expf(s[nt][3] - mn1);
            sum0 += p[nt][0] + p[nt][1];
            sum1 += p[nt][2] + p[nt][3];
        }
        sum0 += __shfl_xor_sync(0xffffffff, sum0, 1);
        sum0 += __shfl_xor_sync(0xffffffff, sum0, 2);
        sum1 += __shfl_xor_sync(0xffffffff, sum1, 1);
        sum1 += __shfl_xor_sync(0xffffffff, sum1, 2);
        l0 = l0 * al0 + sum0;
        l1 = l1 * al1 + sum1;

        #pragma unroll
        for (int nt = 0; nt < 8; nt++) {
            o[nt][0] *= al0; o[nt][1] *= al0;
            o[nt][2] *= al1; o[nt][3] *= al1;
        }

        uint32_t pfh[4][4], pfl[4][4];
        #pragma unroll
        for (int t = 0; t < 4; t++) {
            int n0 = 2 * t, n1 = 2 * t + 1;
            float e[8] = {p[n0][0], p[n0][1], p[n0][2], p[n0][3],
                          p[n1][0], p[n1][1], p[n1][2], p[n1][3]};
            #pragma unroll
            for (int g = 0; g < 4; g++) {
                __nv_bfloat162 hh = __floats2bfloat162_rn(e[2*g], e[2*g+1]);
                pfh[t][g] = *(uint32_t*)&hh;
                __nv_bfloat162 ll = __floats2bfloat162_rn(
                    e[2*g]   - __bfloat162float(hh.x),
                    e[2*g+1] - __bfloat162float(hh.y));
                pfl[t][g] = *(uint32_t*)&ll;
            }
        }

        #pragma unroll
        for (int t = 0; t < 4; t++) {
            #pragma unroll
            for (int jp = 0; jp < 4; jp++) {
                uint32_t vh4[4], vl4[4];
                uint32_t off = swz((uint32_t)((t * 16 + vrow) * 128 + jp * 32 + vcol));
                ldsm4t(vh4, kvb + 16384 + off);
                ldsm4t(vl4, kvb + 24576 + off);
                #pragma unroll
                for (int hf = 0; hf < 2; hf++) {
                    int nt = jp * 2 + hf;
                    const uint32_t* Bh_ = &vh4[hf * 2];
                    const uint32_t* Bl_ = &vl4[hf * 2];
                    mma16816(o[nt], pfh[t], Bh_);
                    mma16816(o[nt], pfl[t], Bh_);
                    mma16816(o[nt], pfh[t], Bl_);
                }
            }
        }
        __syncthreads();
    }

    float inv0 = 1.f / l0;
    float inv1 = 1.f / l1;
    size_t r0g = (size_t)(b * SEQ + grow0) * DMODEL + h * DHEAD;
    size_t r1g = (size_t)(b * SEQ + grow1) * DMODEL + h * DHEAD;
    #pragma unroll
    for (int nt = 0; nt < 8; nt++) {
        int c = nt * 8 + (lane & 3) * 2;
        float v0 = o[nt][0] * inv0, v1 = o[nt][1] * inv0;
        float v2 = o[nt][2] * inv1, v3 = o[nt][3] * inv1;
        __nv_bfloat162 h01 = __floats2bfloat162_rn(v0, v1);
        __nv_bfloat162 l01 = __floats2bfloat162_rn(
            v0 - __bfloat162float(h01.x), v1 - __bfloat162float(h01.y));
        __nv_bfloat162 h23 = __floats2bfloat162_rn(v2, v3);
        __nv_bfloat162 l23 = __floats2bfloat162_rn(
            v2 - __bfloat162float(h23.x), v3 - __bfloat162float(h23.y));
        *(__nv_bfloat162*)(g_ah + r0g + c) = h01;
        *(__nv_bfloat162*)(g_al + r0g + c) = l01;
        *(__nv_bfloat162*)(g_ah + r1g + c) = h23;
        *(__nv_bfloat162*)(g_al + r1g + c) = l23;
    }
}

// ---------------- launch ----------------
extern "C" void kernel_launch(void* const* d_in, const int* in_sizes, int n_in,
                              void* d_out, int out_size)
{
    const float* x  = (const float*)d_in[0];
    const float* Wq = (const float*)d_in[1];
    const float* bq = (const float*)d_in[2];
    const float* Wk = (const float*)d_in[3];
    const float* bk = (const float*)d_in[4];
    const float* Wv = (const float*)d_in[5];
    const float* bv = (const float*)d_in[6];
    const float* Wo = (const float*)d_in[7];
    const float* bo = (const float*)d_in[8];
    float* out = (float*)d_out;

    __nv_bfloat16 *pah, *pal, *pqh, *pql, *pkh, *pkl, *pvh, *pvl;
    cudaGetSymbolAddress((void**)&pah, g_ah);
    cudaGetSymbolAddress((void**)&pal, g_al);
    cudaGetSymbolAddress((void**)&pqh, g_qh);
    cudaGetSymbolAddress((void**)&pql, g_ql);
    cudaGetSymbolAddress((void**)&pkh, g_kh);
    cudaGetSymbolAddress((void**)&pkl, g_kl);
    cudaGetSymbolAddress((void**)&pvh, g_vh);
    cudaGetSymbolAddress((void**)&pvl, g_vl);

    cudaFuncSetAttribute(gemm_big_kernel<1>,
                         cudaFuncAttributeMaxDynamicSharedMemorySize, SM_GEMM_TOTAL);
    cudaFuncSetAttribute(gemm_big_kernel<0>,
                         cudaFuncAttributeMaxDynamicSharedMemorySize, SM_GEMM_TOTAL);
    cudaFuncSetAttribute(flash_mma_kernel,
                         cudaFuncAttributeMaxDynamicSharedMemorySize, SM_FLASH_TOTAL);

    const int nA = MROWS * DMODEL;

    rope_table_kernel<<<SEQ, 32>>>();
    split_kernel<<<nA / 1024, 256>>>(x, pah, pal, nA);
    tsplit4_kernel<<<dim3(32, 32, 4), dim3(32, 8)>>>(Wq, Wk, Wv, Wo);

    // fused Q,K,V projections (2 CTAs/SM, 3-stage pipeline)
    gemm_big_kernel<1><<<dim3(8, 32, 3), 256, SM_GEMM_TOTAL>>>(
        pah, pal, bq, bk, bv,
        pqh, pql, pkh, pkl, pvh, pvl, nullptr);

    // attention: 64-row q tiles, 128 threads, 2 CTAs/SM
    flash_mma_kernel<<<dim3(SEQ / 64, BATCH * NHEADS), 128, SM_FLASH_TOTAL>>>();

    // O projection (weight slot 3, fp32 out)
    gemm_big_kernel<0><<<dim3(8, 32, 1), 256, SM_GEMM_TOTAL>>>(
        pah, pal, bo, nullptr, nullptr,
        nullptr, nullptr, nullptr, nullptr, nullptr, nullptr, out);
}

// round 15
// speedup vs baseline: 1.4457x; 1.2042x over previous
#include <cuda_runtime.h>
#include <cuda_fp16.h>
#include <math.h>
#include <stdint.h>

// ---------------- problem constants ----------------
#define BATCH   2
#define SEQ     2048
#define DMODEL  1024
#define NHEADS  16
#define DHEAD   64
#define MROWS   (BATCH*SEQ)          // 4096
#define SCALE   0.125f

// ---------------- device scratch (fp16 internals) ----------------
__device__ float g_rc[SEQ * 32];
__device__ float g_rs[SEQ * 32];
__device__ __half g_ah[MROWS * DMODEL];       // x hi, later ctx hi
__device__ __half g_al[MROWS * DMODEL];       // x lo, later ctx lo
__device__ __half g_wth[4 * DMODEL * DMODEL]; // W^T fp16 (single term), slots q,k,v,o
__device__ __half g_qh[MROWS * DMODEL];
__device__ __half g_ql[MROWS * DMODEL];
__device__ __half g_kh[MROWS * DMODEL];
__device__ __half g_kl[MROWS * DMODEL];
__device__ __half g_vh[MROWS * DMODEL];
__device__ __half g_vl[MROWS * DMODEL];

// ---------------- PTX helpers (sm_100 base-target safe) ----------------
__device__ __forceinline__ uint32_t smem_u32(const void* p) {
    uint32_t a;
    asm("{ .reg .u64 t; cvta.to.shared.u64 t, %1; cvt.u32.u64 %0, t; }" : "=r"(a) : "l"(p));
    return a;
}
__device__ __forceinline__ void cpasync16(uint32_t sdst, const void* gsrc) {
    asm volatile("cp.async.cg.shared.global [%0], [%1], 16;" :: "r"(sdst), "l"(gsrc));
}
__device__ __forceinline__ void cpasync_commit() {
    asm volatile("cp.async.commit_group;" ::: "memory");
}
__device__ __forceinline__ void ldsm4(uint32_t* d, uint32_t addr) {
    asm volatile("ldmatrix.sync.aligned.m8n8.x4.shared.b16 {%0,%1,%2,%3}, [%4];"
                 : "=r"(d[0]), "=r"(d[1]), "=r"(d[2]), "=r"(d[3]) : "r"(addr));
}
__device__ __forceinline__ void ldsm4t(uint32_t* d, uint32_t addr) {
    asm volatile("ldmatrix.sync.aligned.m8n8.x4.trans.shared.b16 {%0,%1,%2,%3}, [%4];"
                 : "=r"(d[0]), "=r"(d[1]), "=r"(d[2]), "=r"(d[3]) : "r"(addr));
}
// fp16 HMMA, fp32 accumulate
__device__ __forceinline__ void mma16816(float* c, const uint32_t* a, const uint32_t* b) {
    asm volatile(
        "mma.sync.aligned.m16n8k16.row.col.f32.f16.f16.f32 "
        "{%0,%1,%2,%3}, {%4,%5,%6,%7}, {%8,%9}, {%0,%1,%2,%3};"
        : "+f"(c[0]), "+f"(c[1]), "+f"(c[2]), "+f"(c[3])
        : "r"(a[0]), "r"(a[1]), "r"(a[2]), "r"(a[3]), "r"(b[0]), "r"(b[1]));
}
__device__ __forceinline__ uint32_t swz(uint32_t off) {    // 128B-row swizzle
    return off ^ ((off >> 3) & 0x70);
}
__device__ __forceinline__ uint32_t swz64(uint32_t off) {  // 64B-row swizzle
    return off ^ ((off >> 3) & 0x30);
}

// ---------------- RoPE tables ----------------
__global__ void rope_table_kernel() {
    int t = blockIdx.x, i = threadIdx.x;
    float inv = powf(10000.0f, -(2.0f * (float)i) / 64.0f);
    float ang = (float)t * inv;
    g_rc[t * 32 + i] = cosf(ang);
    g_rs[t * 32 + i] = sinf(ang);
}

// ---------------- fp32 -> fp16 hi/lo split ----------------
__global__ __launch_bounds__(256)
void split_kernel(const float* __restrict__ src,
                  __half* __restrict__ hi,
                  __half* __restrict__ lo, int n) {
    int i = (blockIdx.x * 256 + threadIdx.x) * 4;
    if (i >= n) return;
    float4 v = *(const float4*)(src + i);
    float a[4] = {v.x, v.y, v.z, v.w};
    #pragma unroll
    for (int j = 0; j < 4; j++) {
        __half h = __float2half_rn(a[j]);
        hi[i + j] = h;
        lo[i + j] = __float2half_rn(a[j] - __half2float(h));
    }
}

// ---------------- all four W[K][N] -> W^T fp16 [N][K] in one launch ----------------
__global__ __launch_bounds__(256)
void tsplit4_kernel(const float* __restrict__ W0, const float* __restrict__ W1,
                    const float* __restrict__ W2, const float* __restrict__ W3) {
    __shared__ float t[32][33];
    int z  = blockIdx.z;
    const float* W = (z == 0) ? W0 : (z == 1) ? W1 : (z == 2) ? W2 : W3;
    size_t slot = (size_t)z * DMODEL * DMODEL;
    int bn = blockIdx.x * 32;
    int bk = blockIdx.y * 32;
    int x = threadIdx.x, y0 = threadIdx.y;   // 32 x 8
    #pragma unroll
    for (int yy = y0; yy < 32; yy += 8)
        t[yy][x] = W[(size_t)(bk + yy) * DMODEL + bn + x];
    __syncthreads();
    #pragma unroll
    for (int yy = y0; yy < 32; yy += 8) {
        float v = t[x][yy];
        g_wth[slot + (size_t)(bn + yy) * DMODEL + bk + x] = __float2half_rn(v);
    }
}

// ---------------- mma.sync fp16 2-term GEMM ----------------
// C = (Ah+Al) @ Bh^T; dropped term A*(B - Bh) ~ 2^-12 relative.
// CTA 128x128, 8 warps (4m x 2n), warp tile 32x64, K-chunk 32 (SW64 rows),
// 3-stage cp.async pipeline (24KB stages), 2 CTAs/SM.
#define TILE_B    8192
#define STAGE_B   (3 * TILE_B)            // Ah,Al,Bh = 24KB
#define SM_GEMM_TOTAL (3 * STAGE_B)       // 73728

template<int FUSED>
__global__ __launch_bounds__(256, 2)
void gemm_big_kernel(const __half* __restrict__ Ah,
                     const __half* __restrict__ Al,
                     const float* __restrict__ b0,
                     const float* __restrict__ b1,
                     const float* __restrict__ b2,
                     __half* __restrict__ o0h, __half* __restrict__ o0l,
                     __half* __restrict__ o1h, __half* __restrict__ o1l,
                     __half* __restrict__ o2h, __half* __restrict__ o2l,
                     float* __restrict__ Cf)
{
    extern __shared__ char smem[];
    uint32_t sb = smem_u32(smem);
    int tid  = threadIdx.x;
    int wid  = tid >> 5;
    int lane = tid & 31;
    int row0 = blockIdx.y * 128;
    int col0 = blockIdx.x * 128;
    int z    = FUSED ? blockIdx.z : 3;

    const __half* srcAh = Ah + (size_t)row0 * DMODEL;
    const __half* srcAl = Al + (size_t)row0 * DMODEL;
    const __half* srcBh = g_wth + (size_t)z * DMODEL * DMODEL + (size_t)col0 * DMODEL;

    int m0w = (wid & 3) * 32;
    int n0w = (wid >> 2) * 64;

    float acc[2][8][4];
    #pragma unroll
    for (int i = 0; i < 2; i++)
        #pragma unroll
        for (int j = 0; j < 8; j++)
            #pragma unroll
            for (int r = 0; r < 4; r++) acc[i][j][r] = 0.f;

    auto prefetch = [&](int s, uint32_t base) {
        int kc = s * 32;
        #pragma unroll
        for (int i = 0; i < 2; i++) {
            int flat = i * 256 + tid;
            int r  = flat >> 2;
            int ch = flat & 3;
            uint32_t sw = swz64((uint32_t)(r * 64 + ch * 16));
            size_t go = (size_t)r * DMODEL + kc + ch * 8;
            cpasync16(base + 0 * TILE_B + sw, srcAh + go);
            cpasync16(base + 1 * TILE_B + sw, srcAl + go);
            cpasync16(base + 2 * TILE_B + sw, srcBh + go);
        }
        cpasync_commit();
    };

    prefetch(0, sb);
    prefetch(1, sb + STAGE_B);

    int raA = (lane & 15);
    int caA = (lane >> 4) * 16;
    int rbB = ((lane >> 4) << 3) + (lane & 7);
    int cbB = ((lane >> 3) & 1) * 16;

    for (int s = 0; s < 32; s++) {
        if (s + 2 < 32) {
            prefetch(s + 2, sb + (uint32_t)((s + 2) % 3) * STAGE_B);
            asm volatile("cp.async.wait_group 2;" ::: "memory");
        } else if (s + 1 < 32) {
            asm volatile("cp.async.wait_group 1;" ::: "memory");
        } else {
            asm volatile("cp.async.wait_group 0;" ::: "memory");
        }
        __syncthreads();

        uint32_t base = sb + (uint32_t)(s % 3) * STAGE_B;
        uint32_t bAh = base;
        uint32_t bAl = base + TILE_B;
        uint32_t bBh = base + 2 * TILE_B;

        #pragma unroll
        for (int kk = 0; kk < 2; kk++) {
            int cb = kk * 32;
            uint32_t ah[2][4], al[2][4];
            #pragma unroll
            for (int i = 0; i < 2; i++) {
                uint32_t off = swz64((uint32_t)((m0w + i * 16 + raA) * 64 + cb + caA));
                ldsm4(ah[i], bAh + off);
                ldsm4(al[i], bAl + off);
            }
            #pragma unroll
            for (int jp = 0; jp < 4; jp++) {
                uint32_t bh4[4];
                uint32_t off = swz64((uint32_t)((n0w + jp * 16 + rbB) * 64 + cb + cbB));
                ldsm4(bh4, bBh + off);
                #pragma unroll
                for (int i = 0; i < 2; i++) {
                    #pragma unroll
                    for (int hf = 0; hf < 2; hf++) {
                        int j = jp * 2 + hf;
                        const uint32_t* Bhf = &bh4[hf * 2];
                        mma16816(acc[i][j], ah[i], Bhf);
                        mma16816(acc[i][j], al[i], Bhf);
                    }
                }
            }
        }
        __syncthreads();
    }

    const float* bias;
    __half *Ch, *Cl;
    int applyRope;
    if (FUSED) {
        bias = (z == 0) ? b0 : (z == 1) ? b1 : b2;
        Ch   = (z == 0) ? o0h : (z == 1) ? o1h : o2h;
        Cl   = (z == 0) ? o0l : (z == 1) ? o1l : o2l;
        applyRope = (z < 2);
    } else {
        bias = b0; Ch = nullptr; Cl = nullptr; applyRope = 0;
    }

    #pragma unroll
    for (int i = 0; i < 2; i++) {
        int m_lo = row0 + m0w + i * 16 + (lane >> 2);
        int m_hi = m_lo + 8;
        int s_lo = m_lo & (SEQ - 1);
        int s_hi = m_hi & (SEQ - 1);
        #pragma unroll
        for (int j = 0; j < 8; j++) {
            int n = col0 + n0w + j * 8 + (lane & 3) * 2;
            float bb0 = bias[n], bb1 = bias[n + 1];
            float v0 = acc[i][j][0] + bb0;
            float v1 = acc[i][j][1] + bb1;
            float v2 = acc[i][j][2] + bb0;
            float v3 = acc[i][j][3] + bb1;
            if (applyRope) {
                int pi = (n & 63) >> 1;
                float c0 = g_rc[s_lo * 32 + pi], s0 = g_rs[s_lo * 32 + pi];
                float c1 = g_rc[s_hi * 32 + pi], s1 = g_rs[s_hi * 32 + pi];
                float t0 = v0 * c0 - v1 * s0;
                float t1 = v0 * s0 + v1 * c0;
                float t2 = v2 * c1 - v3 * s1;
                float t3 = v2 * s1 + v3 * c1;
                v0 = t0; v1 = t1; v2 = t2; v3 = t3;
            }
            if (FUSED) {
                __half2 h01 = __floats2half2_rn(v0, v1);
                __half2 l01 = __floats2half2_rn(
                    v0 - __half2float(h01.x), v1 - __half2float(h01.y));
                __half2 h23 = __floats2half2_rn(v2, v3);
                __half2 l23 = __floats2half2_rn(
                    v2 - __half2float(h23.x), v3 - __half2float(h23.y));
                *(__half2*)(Ch + (size_t)m_lo * DMODEL + n) = h01;
                *(__half2*)(Cl + (size_t)m_lo * DMODEL + n) = l01;
                *(__half2*)(Ch + (size_t)m_hi * DMODEL + n) = h23;
                *(__half2*)(Cl + (size_t)m_hi * DMODEL + n) = l23;
            } else {
                *(float2*)(Cf + (size_t)m_lo * DMODEL + n) = make_float2(v0, v1);
                *(float2*)(Cf + (size_t)m_hi * DMODEL + n) = make_float2(v2, v3);
            }
        }
    }
}

// ---------------- flash attention: fp16 3-term, 64 q-rows / 128 threads / 2 CTAs ----------------
#define FSQ_H   0
#define FSQ_L   8192
#define FSKV    16384
#define FKV_STAGE 32768
#define SM_FLASH_TOTAL (FSKV + 2 * FKV_STAGE)   // 81920

__global__ __launch_bounds__(128)
void flash_mma_kernel()
{
    extern __shared__ char smem[];
    uint32_t sb = smem_u32(smem);
    int tid  = threadIdx.x;
    int wid  = tid >> 5;          // 0..3
    int lane = tid & 31;
    int iq   = gridDim.x - 1 - blockIdx.x;   // big causal tiles first
    int bh   = blockIdx.y;
    int b    = bh >> 4;
    int h    = bh & 15;

    const size_t hb = (size_t)(b * SEQ) * DMODEL + h * DHEAD;
    const __half* Qh = g_qh + hb + (size_t)iq * 64 * DMODEL;
    const __half* Ql = g_ql + hb + (size_t)iq * 64 * DMODEL;

    #pragma unroll
    for (int i = 0; i < 4; i++) {
        int flat = i * 128 + tid;
        int r  = flat >> 3;
        int ch = flat & 7;
        uint32_t sw = swz((uint32_t)(r * 128 + ch * 16));
        size_t go = (size_t)r * DMODEL + ch * 8;
        cpasync16(sb + FSQ_H + sw, Qh + go);
        cpasync16(sb + FSQ_L + sw, Ql + go);
    }

    auto prefetch_kv = [&](int j) {
        uint32_t base = sb + FSKV + (uint32_t)(j & 1) * FKV_STAGE;
        const __half* kh = g_kh + hb + (size_t)j * 64 * DMODEL;
        const __half* kl = g_kl + hb + (size_t)j * 64 * DMODEL;
        const __half* vh = g_vh + hb + (size_t)j * 64 * DMODEL;
        const __half* vl = g_vl + hb + (size_t)j * 64 * DMODEL;
        #pragma unroll
        for (int i = 0; i < 4; i++) {
            int flat = i * 128 + tid;
            int r  = flat >> 3;
            int ch = flat & 7;
            uint32_t sw = swz((uint32_t)(r * 128 + ch * 16));
            size_t go = (size_t)r * DMODEL + ch * 8;
            cpasync16(base + 0     + sw, kh + go);
            cpasync16(base + 8192  + sw, kl + go);
            cpasync16(base + 16384 + sw, vh + go);
            cpasync16(base + 24576 + sw, vl + go);
        }
        cpasync_commit();
    };

    prefetch_kv(0);   // group 0 includes Q

    const int nblocks = iq + 1;
    const int q0 = wid * 16;

    int raA = (lane & 15);
    int caA = (lane >> 4) * 16;
    int rbB = ((lane >> 4) << 3) + (lane & 7);
    int cbB = ((lane >> 3) & 1) * 16;
    int vrow = lane & 15;
    int vcol = (lane >> 4) * 16;

    const int grow0 = iq * 64 + q0 + (lane >> 2);
    const int grow1 = grow0 + 8;

    float o[8][4];
    #pragma unroll
    for (int j = 0; j < 8; j++)
        #pragma unroll
        for (int r = 0; r < 4; r++) o[j][r] = 0.f;
    float m0 = -1e30f, m1 = -1e30f, l0 = 0.f, l1 = 0.f;

    uint32_t qfh[4][4], qfl[4][4];
    bool qloaded = false;

    for (int jb = 0; jb < nblocks; jb++) {
        if (jb + 1 < nblocks) {
            prefetch_kv(jb + 1);
            asm volatile("cp.async.wait_group 1;" ::: "memory");
        } else {
            asm volatile("cp.async.wait_group 0;" ::: "memory");
        }
        __syncthreads();

        if (!qloaded) {
            #pragma unroll
            for (int kk = 0; kk < 4; kk++) {
                uint32_t off = swz((uint32_t)((q0 + raA) * 128 + kk * 32 + caA));
                ldsm4(qfh[kk], sb + FSQ_H + off);
                ldsm4(qfl[kk], sb + FSQ_L + off);
            }
            qloaded = true;
        }

        uint32_t kvb = sb + FSKV + (uint32_t)(jb & 1) * FKV_STAGE;

        float s[8][4];
        #pragma unroll
        for (int j = 0; j < 8; j++)
            #pragma unroll
            for (int r = 0; r < 4; r++) s[j][r] = 0.f;

        #pragma unroll
        for (int kk = 0; kk < 4; kk++) {
            #pragma unroll
            for (int jp = 0; jp < 4; jp++) {
                uint32_t kh4[4], kl4[4];
                uint32_t off = swz((uint32_t)((jp * 16 + rbB) * 128 + kk * 32 + cbB));
                ldsm4(kh4, kvb + 0    + off);
                ldsm4(kl4, kvb + 8192 + off);
                #pragma unroll
                for (int hf = 0; hf < 2; hf++) {
                    int nt = jp * 2 + hf;
                    const uint32_t* Bh_ = &kh4[hf * 2];
                    const uint32_t* Bl_ = &kl4[hf * 2];
                    mma16816(s[nt], qfh[kk], Bh_);
                    mma16816(s[nt], qfh[kk], Bl_);
                    mma16816(s[nt], qfl[kk], Bh_);
                }
            }
        }

        int kv0 = jb * 64;
        #pragma unroll
        for (int nt = 0; nt < 8; nt++)
            #pragma unroll
            for (int r = 0; r < 4; r++) s[nt][r] *= SCALE;
        if (kv0 + 63 > grow0) {
            #pragma unroll
            for (int nt = 0; nt < 8; nt++) {
                int c = kv0 + nt * 8 + (lane & 3) * 2;
                if (c > grow0)     s[nt][0] = -1e30f;
                if (c + 1 > grow0) s[nt][1] = -1e30f;
                if (c > grow1)     s[nt][2] = -1e30f;
                if (c + 1 > grow1) s[nt][3] = -1e30f;
            }
        }

        float mxa = -1e30f, mxb = -1e30f;
        #pragma unroll
        for (int nt = 0; nt < 8; nt++) {
            mxa = fmaxf(mxa, fmaxf(s[nt][0], s[nt][1]));
            mxb = fmaxf(mxb, fmaxf(s[nt][2], s[nt][3]));
        }
        mxa = fmaxf(mxa, __shfl_xor_sync(0xffffffff, mxa, 1));
        mxa = fmaxf(mxa, __shfl_xor_sync(0xffffffff, mxa, 2));
        mxb = fmaxf(mxb, __shfl_xor_sync(0xffffffff, mxb, 1));
        mxb = fmaxf(mxb, __shfl_xor_sync(0xffffffff, mxb, 2));
        float mn0 = fmaxf(m0, mxa);
        float mn1 = fmaxf(m1, mxb);
        float al0 = __expf(m0 - mn0);
        float al1 = __expf(m1 - mn1);
        m0 = mn0; m1 = mn1;

        float p[8][4];
        float sum0 = 0.f, sum1 = 0.f;
        #pragma unroll
        for (int nt = 0; nt < 8; nt++) {
            p[nt][0] = __expf(s[nt][0] - mn0);
            p[nt][1] = __expf(s[nt][1] - mn0);
            p[nt][2] = __expf(s[nt][2] - mn1);
            p[nt][3] = __expf(s[nt][3] - mn1);
            sum0 += p[nt][0] + p[nt][1];
            sum1 += p[nt][2] + p[nt][3];
        }
        sum0 += __shfl_xor_sync(0xffffffff, sum0, 1);
        sum0 += __shfl_xor_sync(0xffffffff, sum0, 2);
        sum1 += __shfl_xor_sync(0xffffffff, sum1, 1);
        sum1 += __shfl_xor_sync(0xffffffff, sum1, 2);
        l0 = l0 * al0 + sum0;
        l1 = l1 * al1 + sum1;

        #pragma unroll
        for (int nt = 0; nt < 8; nt++) {
            o[nt][0] *= al0; o[nt][1] *= al0;
            o[nt][2] *= al1; o[nt][3] *= al1;
        }

        uint32_t pfh[4][4], pfl[4][4];
        #pragma unroll
        for (int t = 0; t < 4; t++) {
            int n0 = 2 * t, n1 = 2 * t + 1;
            float e[8] = {p[n0][0], p[n0][1], p[n0][2], p[n0][3],
                          p[n1][0], p[n1][1], p[n1][2], p[n1][3]};
            #pragma unroll
            for (int g = 0; g < 4; g++) {
                __half2 hh = __floats2half2_rn(e[2*g], e[2*g+1]);
                pfh[t][g] = *(uint32_t*)&hh;
                __half2 ll = __floats2half2_rn(
                    e[2*g]   - __half2float(hh.x),
                    e[2*g+1] - __half2float(hh.y));
                pfl[t][g] = *(uint32_t*)&ll;
            }
        }

        #pragma unroll
        for (int t = 0; t < 4; t++) {
            #pragma unroll
            for (int jp = 0; jp < 4; jp++) {
                uint32_t vh4[4], vl4[4];
                uint32_t off = swz((uint32_t)((t * 16 + vrow) * 128 + jp * 32 + vcol));
                ldsm4t(vh4, kvb + 16384 + off);
                ldsm4t(vl4, kvb + 24576 + off);
                #pragma unroll
                for (int hf = 0; hf < 2; hf++) {
                    int nt = jp * 2 + hf;
                    const uint32_t* Bh_ = &vh4[hf * 2];
                    const uint32_t* Bl_ = &vl4[hf * 2];
                    mma16816(o[nt], pfh[t], Bh_);
                    mma16816(o[nt], pfl[t], Bh_);
                    mma16816(o[nt], pfh[t], Bl_);
                }
            }
        }
        __syncthreads();
    }

    float inv0 = 1.f / l0;
    float inv1 = 1.f / l1;
    size_t r0g = (size_t)(b * SEQ + grow0) * DMODEL + h * DHEAD;
    size_t r1g = (size_t)(b * SEQ + grow1) * DMODEL + h * DHEAD;
    #pragma unroll
    for (int nt = 0; nt < 8; nt++) {
        int c = nt * 8 + (lane & 3) * 2;
        float v0 = o[nt][0] * inv0, v1 = o[nt][1] * inv0;
        float v2 = o[nt][2] * inv1, v3 = o[nt][3] * inv1;
        __half2 h01 = __floats2half2_rn(v0, v1);
        __half2 l01 = __floats2half2_rn(
            v0 - __half2float(h01.x), v1 - __half2float(h01.y));
        __half2 h23 = __floats2half2_rn(v2, v3);
        __half2 l23 = __floats2half2_rn(
            v2 - __half2float(h23.x), v3 - __half2float(h23.y));
        *(__half2*)(g_ah + r0g + c) = h01;
        *(__half2*)(g_al + r0g + c) = l01;
        *(__half2*)(g_ah + r1g + c) = h23;
        *(__half2*)(g_al + r1g + c) = l23;
    }
}

// ---------------- launch ----------------
extern "C" void kernel_launch(void* const* d_in, const int* in_sizes, int n_in,
                              void* d_out, int out_size)
{
    const float* x  = (const float*)d_in[0];
    const float* Wq = (const float*)d_in[1];
    const float* bq = (const float*)d_in[2];
    const float* Wk = (const float*)d_in[3];
    const float* bk = (const float*)d_in[4];
    const float* Wv = (const float*)d_in[5];
    const float* bv = (const float*)d_in[6];
    const float* Wo = (const float*)d_in[7];
    const float* bo = (const float*)d_in[8];
    float* out = (float*)d_out;

    __half *pah, *pal, *pqh, *pql, *pkh, *pkl, *pvh, *pvl;
    cudaGetSymbolAddress((void**)&pah, g_ah);
    cudaGetSymbolAddress((void**)&pal, g_al);
    cudaGetSymbolAddress((void**)&pqh, g_qh);
    cudaGetSymbolAddress((void**)&pql, g_ql);
    cudaGetSymbolAddress((void**)&pkh, g_kh);
    cudaGetSymbolAddress((void**)&pkl, g_kl);
    cudaGetSymbolAddress((void**)&pvh, g_vh);
    cudaGetSymbolAddress((void**)&pvl, g_vl);

    cudaFuncSetAttribute(gemm_big_kernel<1>,
                         cudaFuncAttributeMaxDynamicSharedMemorySize, SM_GEMM_TOTAL);
    cudaFuncSetAttribute(gemm_big_kernel<0>,
                         cudaFuncAttributeMaxDynamicSharedMemorySize, SM_GEMM_TOTAL);
    cudaFuncSetAttribute(flash_mma_kernel,
                         cudaFuncAttributeMaxDynamicSharedMemorySize, SM_FLASH_TOTAL);

    const int nA = MROWS * DMODEL;

    rope_table_kernel<<<SEQ, 32>>>();
    split_kernel<<<nA / 1024, 256>>>(x, pah, pal, nA);
    tsplit4_kernel<<<dim3(32, 32, 4), dim3(32, 8)>>>(Wq, Wk, Wv, Wo);

    // fused Q,K,V projections (2 CTAs/SM, 3-stage pipeline, 2-term fp16)
    gemm_big_kernel<1><<<dim3(8, 32, 3), 256, SM_GEMM_TOTAL>>>(
        pah, pal, bq, bk, bv,
        pqh, pql, pkh, pkl, pvh, pvl, nullptr);

    // attention: 64-row q tiles, 128 threads, 2 CTAs/SM, fp16 3-term
    flash_mma_kernel<<<dim3(SEQ / 64, BATCH * NHEADS), 128, SM_FLASH_TOTAL>>>();

    // O projection (weight slot 3, fp32 out)
    gemm_big_kernel<0><<<dim3(8, 32, 1), 256, SM_GEMM_TOTAL>>>(
        pah, pal, bo, nullptr, nullptr,
        nullptr, nullptr, nullptr, nullptr, nullptr, nullptr, out);
}

// round 16
// speedup vs baseline: 1.5389x; 1.0645x over previous
#include <cuda_runtime.h>
#include <cuda_fp16.h>
#include <math.h>
#include <stdint.h>

// ---------------- problem constants ----------------
#define BATCH   2
#define SEQ     2048
#define DMODEL  1024
#define NHEADS  16
#define DHEAD   64
#define MROWS   (BATCH*SEQ)          // 4096
#define SCALE   0.125f

// ---------------- device scratch (fp16 internals) ----------------
__device__ float g_rc[SEQ * 32];
__device__ float g_rs[SEQ * 32];
__device__ __half g_ah[MROWS * DMODEL];       // x hi, later ctx hi
__device__ __half g_al[MROWS * DMODEL];       // x lo, later ctx lo
__device__ __half g_wth[4 * DMODEL * DMODEL]; // W^T fp16 (single term), slots q,k,v,o
__device__ __half g_qh[MROWS * DMODEL];
__device__ __half g_ql[MROWS * DMODEL];
__device__ __half g_kh[MROWS * DMODEL];
__device__ __half g_kl[MROWS * DMODEL];
__device__ __half g_vh[MROWS * DMODEL];
__device__ __half g_vl[MROWS * DMODEL];

// ---------------- PTX helpers (sm_100 base-target safe) ----------------
__device__ __forceinline__ uint32_t smem_u32(const void* p) {
    uint32_t a;
    asm("{ .reg .u64 t; cvta.to.shared.u64 t, %1; cvt.u32.u64 %0, t; }" : "=r"(a) : "l"(p));
    return a;
}
__device__ __forceinline__ void cpasync16(uint32_t sdst, const void* gsrc) {
    asm volatile("cp.async.cg.shared.global [%0], [%1], 16;" :: "r"(sdst), "l"(gsrc));
}
__device__ __forceinline__ void cpasync_commit() {
    asm volatile("cp.async.commit_group;" ::: "memory");
}
__device__ __forceinline__ void ldsm4(uint32_t* d, uint32_t addr) {
    asm volatile("ldmatrix.sync.aligned.m8n8.x4.shared.b16 {%0,%1,%2,%3}, [%4];"
                 : "=r"(d[0]), "=r"(d[1]), "=r"(d[2]), "=r"(d[3]) : "r"(addr));
}
__device__ __forceinline__ void ldsm4t(uint32_t* d, uint32_t addr) {
    asm volatile("ldmatrix.sync.aligned.m8n8.x4.trans.shared.b16 {%0,%1,%2,%3}, [%4];"
                 : "=r"(d[0]), "=r"(d[1]), "=r"(d[2]), "=r"(d[3]) : "r"(addr));
}
// fp16 HMMA, fp32 accumulate
__device__ __forceinline__ void mma16816(float* c, const uint32_t* a, const uint32_t* b) {
    asm volatile(
        "mma.sync.aligned.m16n8k16.row.col.f32.f16.f16.f32 "
        "{%0,%1,%2,%3}, {%4,%5,%6,%7}, {%8,%9}, {%0,%1,%2,%3};"
        : "+f"(c[0]), "+f"(c[1]), "+f"(c[2]), "+f"(c[3])
        : "r"(a[0]), "r"(a[1]), "r"(a[2]), "r"(a[3]), "r"(b[0]), "r"(b[1]));
}
__device__ __forceinline__ uint32_t swz(uint32_t off) {    // 128B-row swizzle
    return off ^ ((off >> 3) & 0x70);
}
__device__ __forceinline__ uint32_t swz64(uint32_t off) {  // 64B-row swizzle
    return off ^ ((off >> 3) & 0x30);
}

// ---------------- RoPE tables ----------------
__global__ void rope_table_kernel() {
    int t = blockIdx.x, i = threadIdx.x;
    float inv = powf(10000.0f, -(2.0f * (float)i) / 64.0f);
    float ang = (float)t * inv;
    g_rc[t * 32 + i] = cosf(ang);
    g_rs[t * 32 + i] = sinf(ang);
}

// ---------------- fp32 -> fp16 hi/lo split ----------------
__global__ __launch_bounds__(256)
void split_kernel(const float* __restrict__ src,
                  __half* __restrict__ hi,
                  __half* __restrict__ lo, int n) {
    int i = (blockIdx.x * 256 + threadIdx.x) * 4;
    if (i >= n) return;
    float4 v = *(const float4*)(src + i);
    float a[4] = {v.x, v.y, v.z, v.w};
    #pragma unroll
    for (int j = 0; j < 4; j++) {
        __half h = __float2half_rn(a[j]);
        hi[i + j] = h;
        lo[i + j] = __float2half_rn(a[j] - __half2float(h));
    }
}

// ---------------- all four W[K][N] -> W^T fp16 [N][K] in one launch ----------------
__global__ __launch_bounds__(256)
void tsplit4_kernel(const float* __restrict__ W0, const float* __restrict__ W1,
                    const float* __restrict__ W2, const float* __restrict__ W3) {
    __shared__ float t[32][33];
    int z  = blockIdx.z;
    const float* W = (z == 0) ? W0 : (z == 1) ? W1 : (z == 2) ? W2 : W3;
    size_t slot = (size_t)z * DMODEL * DMODEL;
    int bn = blockIdx.x * 32;
    int bk = blockIdx.y * 32;
    int x = threadIdx.x, y0 = threadIdx.y;   // 32 x 8
    #pragma unroll
    for (int yy = y0; yy < 32; yy += 8)
        t[yy][x] = W[(size_t)(bk + yy) * DMODEL + bn + x];
    __syncthreads();
    #pragma unroll
    for (int yy = y0; yy < 32; yy += 8) {
        float v = t[x][yy];
        g_wth[slot + (size_t)(bn + yy) * DMODEL + bk + x] = __float2half_rn(v);
    }
}

// ---------------- mma.sync fp16 2-term GEMM ----------------
// C = (Ah+Al) @ Bh^T; single barrier per stage (prefetch after leading sync:
// prefetch(s+2) writes buf (s+2)%3, last read at stage s-1, ordered by sync).
#define TILE_B    8192
#define STAGE_B   (3 * TILE_B)            // Ah,Al,Bh = 24KB
#define SM_GEMM_TOTAL (3 * STAGE_B)       // 73728

template<int FUSED>
__global__ __launch_bounds__(256, 2)
void gemm_big_kernel(const __half* __restrict__ Ah,
                     const __half* __restrict__ Al,
                     const float* __restrict__ b0,
                     const float* __restrict__ b1,
                     const float* __restrict__ b2,
                     __half* __restrict__ o0h, __half* __restrict__ o0l,
                     __half* __restrict__ o1h, __half* __restrict__ o1l,
                     __half* __restrict__ o2h, __half* __restrict__ o2l,
                     float* __restrict__ Cf)
{
    extern __shared__ char smem[];
    uint32_t sb = smem_u32(smem);
    int tid  = threadIdx.x;
    int wid  = tid >> 5;
    int lane = tid & 31;
    int row0 = blockIdx.y * 128;
    int col0 = blockIdx.x * 128;
    int z    = FUSED ? blockIdx.z : 3;

    const __half* srcAh = Ah + (size_t)row0 * DMODEL;
    const __half* srcAl = Al + (size_t)row0 * DMODEL;
    const __half* srcBh = g_wth + (size_t)z * DMODEL * DMODEL + (size_t)col0 * DMODEL;

    int m0w = (wid & 3) * 32;
    int n0w = (wid >> 2) * 64;

    float acc[2][8][4];
    #pragma unroll
    for (int i = 0; i < 2; i++)
        #pragma unroll
        for (int j = 0; j < 8; j++)
            #pragma unroll
            for (int r = 0; r < 4; r++) acc[i][j][r] = 0.f;

    auto prefetch = [&](int s, uint32_t base) {
        int kc = s * 32;
        #pragma unroll
        for (int i = 0; i < 2; i++) {
            int flat = i * 256 + tid;
            int r  = flat >> 2;
            int ch = flat & 3;
            uint32_t sw = swz64((uint32_t)(r * 64 + ch * 16));
            size_t go = (size_t)r * DMODEL + kc + ch * 8;
            cpasync16(base + 0 * TILE_B + sw, srcAh + go);
            cpasync16(base + 1 * TILE_B + sw, srcAl + go);
            cpasync16(base + 2 * TILE_B + sw, srcBh + go);
        }
        cpasync_commit();
    };

    prefetch(0, sb);
    prefetch(1, sb + STAGE_B);

    int raA = (lane & 15);
    int caA = (lane >> 4) * 16;
    int rbB = ((lane >> 4) << 3) + (lane & 7);
    int cbB = ((lane >> 3) & 1) * 16;

    for (int s = 0; s < 32; s++) {
        if (s + 1 < 32) {
            asm volatile("cp.async.wait_group 1;" ::: "memory");
        } else {
            asm volatile("cp.async.wait_group 0;" ::: "memory");
        }
        __syncthreads();
        if (s + 2 < 32)
            prefetch(s + 2, sb + (uint32_t)((s + 2) % 3) * STAGE_B);

        uint32_t base = sb + (uint32_t)(s % 3) * STAGE_B;
        uint32_t bAh = base;
        uint32_t bAl = base + TILE_B;
        uint32_t bBh = base + 2 * TILE_B;

        #pragma unroll
        for (int kk = 0; kk < 2; kk++) {
            int cb = kk * 32;
            uint32_t ah[2][4], al[2][4];
            #pragma unroll
            for (int i = 0; i < 2; i++) {
                uint32_t off = swz64((uint32_t)((m0w + i * 16 + raA) * 64 + cb + caA));
                ldsm4(ah[i], bAh + off);
                ldsm4(al[i], bAl + off);
            }
            #pragma unroll
            for (int jp = 0; jp < 4; jp++) {
                uint32_t bh4[4];
                uint32_t off = swz64((uint32_t)((n0w + jp * 16 + rbB) * 64 + cb + cbB));
                ldsm4(bh4, bBh + off);
                #pragma unroll
                for (int i = 0; i < 2; i++) {
                    #pragma unroll
                    for (int hf = 0; hf < 2; hf++) {
                        int j = jp * 2 + hf;
                        const uint32_t* Bhf = &bh4[hf * 2];
                        mma16816(acc[i][j], ah[i], Bhf);
                        mma16816(acc[i][j], al[i], Bhf);
                    }
                }
            }
        }
    }

    const float* bias;
    __half *Ch, *Cl;
    int applyRope;
    if (FUSED) {
        bias = (z == 0) ? b0 : (z == 1) ? b1 : b2;
        Ch   = (z == 0) ? o0h : (z == 1) ? o1h : o2h;
        Cl   = (z == 0) ? o0l : (z == 1) ? o1l : o2l;
        applyRope = (z < 2);
    } else {
        bias = b0; Ch = nullptr; Cl = nullptr; applyRope = 0;
    }

    #pragma unroll
    for (int i = 0; i < 2; i++) {
        int m_lo = row0 + m0w + i * 16 + (lane >> 2);
        int m_hi = m_lo + 8;
        int s_lo = m_lo & (SEQ - 1);
        int s_hi = m_hi & (SEQ - 1);
        #pragma unroll
        for (int j = 0; j < 8; j++) {
            int n = col0 + n0w + j * 8 + (lane & 3) * 2;
            float bb0 = bias[n], bb1 = bias[n + 1];
            float v0 = acc[i][j][0] + bb0;
            float v1 = acc[i][j][1] + bb1;
            float v2 = acc[i][j][2] + bb0;
            float v3 = acc[i][j][3] + bb1;
            if (applyRope) {
                int pi = (n & 63) >> 1;
                float c0 = g_rc[s_lo * 32 + pi], s0 = g_rs[s_lo * 32 + pi];
                float c1 = g_rc[s_hi * 32 + pi], s1 = g_rs[s_hi * 32 + pi];
                float t0 = v0 * c0 - v1 * s0;
                float t1 = v0 * s0 + v1 * c0;
                float t2 = v2 * c1 - v3 * s1;
                float t3 = v2 * s1 + v3 * c1;
                v0 = t0; v1 = t1; v2 = t2; v3 = t3;
            }
            if (FUSED) {
                __half2 h01 = __floats2half2_rn(v0, v1);
                __half2 l01 = __floats2half2_rn(
                    v0 - __half2float(h01.x), v1 - __half2float(h01.y));
                __half2 h23 = __floats2half2_rn(v2, v3);
                __half2 l23 = __floats2half2_rn(
                    v2 - __half2float(h23.x), v3 - __half2float(h23.y));
                *(__half2*)(Ch + (size_t)m_lo * DMODEL + n) = h01;
                *(__half2*)(Cl + (size_t)m_lo * DMODEL + n) = l01;
                *(__half2*)(Ch + (size_t)m_hi * DMODEL + n) = h23;
                *(__half2*)(Cl + (size_t)m_hi * DMODEL + n) = l23;
            } else {
                *(float2*)(Cf + (size_t)m_lo * DMODEL + n) = make_float2(v0, v1);
                *(float2*)(Cf + (size_t)m_hi * DMODEL + n) = make_float2(v2, v3);
            }
        }
    }
}

// ---------------- flash attention: fp16, QK 3-term, PV 2-term (P single fp16) ----------------
#define FSQ_H   0
#define FSQ_L   8192
#define FSKV    16384
#define FKV_STAGE 32768
#define SM_FLASH_TOTAL (FSKV + 2 * FKV_STAGE)   // 81920

__global__ __launch_bounds__(128)
void flash_mma_kernel()
{
    extern __shared__ char smem[];
    uint32_t sb = smem_u32(smem);
    int tid  = threadIdx.x;
    int wid  = tid >> 5;          // 0..3
    int lane = tid & 31;
    int iq   = gridDim.x - 1 - blockIdx.x;   // big causal tiles first
    int bh   = blockIdx.y;
    int b    = bh >> 4;
    int h    = bh & 15;

    const size_t hb = (size_t)(b * SEQ) * DMODEL + h * DHEAD;
    const __half* Qh = g_qh + hb + (size_t)iq * 64 * DMODEL;
    const __half* Ql = g_ql + hb + (size_t)iq * 64 * DMODEL;

    #pragma unroll
    for (int i = 0; i < 4; i++) {
        int flat = i * 128 + tid;
        int r  = flat >> 3;
        int ch = flat & 7;
        uint32_t sw = swz((uint32_t)(r * 128 + ch * 16));
        size_t go = (size_t)r * DMODEL + ch * 8;
        cpasync16(sb + FSQ_H + sw, Qh + go);
        cpasync16(sb + FSQ_L + sw, Ql + go);
    }

    auto prefetch_kv = [&](int j) {
        uint32_t base = sb + FSKV + (uint32_t)(j & 1) * FKV_STAGE;
        const __half* kh = g_kh + hb + (size_t)j * 64 * DMODEL;
        const __half* kl = g_kl + hb + (size_t)j * 64 * DMODEL;
        const __half* vh = g_vh + hb + (size_t)j * 64 * DMODEL;
        const __half* vl = g_vl + hb + (size_t)j * 64 * DMODEL;
        #pragma unroll
        for (int i = 0; i < 4; i++) {
            int flat = i * 128 + tid;
            int r  = flat >> 3;
            int ch = flat & 7;
            uint32_t sw = swz((uint32_t)(r * 128 + ch * 16));
            size_t go = (size_t)r * DMODEL + ch * 8;
            cpasync16(base + 0     + sw, kh + go);
            cpasync16(base + 8192  + sw, kl + go);
            cpasync16(base + 16384 + sw, vh + go);
            cpasync16(base + 24576 + sw, vl + go);
        }
        cpasync_commit();
    };

    prefetch_kv(0);   // group 0 includes Q

    const int nblocks = iq + 1;
    const int q0 = wid * 16;

    int raA = (lane & 15);
    int caA = (lane >> 4) * 16;
    int rbB = ((lane >> 4) << 3) + (lane & 7);
    int cbB = ((lane >> 3) & 1) * 16;
    int vrow = lane & 15;
    int vcol = (lane >> 4) * 16;

    const int grow0 = iq * 64 + q0 + (lane >> 2);
    const int grow1 = grow0 + 8;

    float o[8][4];
    #pragma unroll
    for (int j = 0; j < 8; j++)
        #pragma unroll
        for (int r = 0; r < 4; r++) o[j][r] = 0.f;
    float m0 = -1e30f, m1 = -1e30f, l0 = 0.f, l1 = 0.f;

    uint32_t qfh[4][4], qfl[4][4];
    bool qloaded = false;

    for (int jb = 0; jb < nblocks; jb++) {
        if (jb + 1 < nblocks) {
            prefetch_kv(jb + 1);
            asm volatile("cp.async.wait_group 1;" ::: "memory");
        } else {
            asm volatile("cp.async.wait_group 0;" ::: "memory");
        }
        __syncthreads();

        if (!qloaded) {
            #pragma unroll
            for (int kk = 0; kk < 4; kk++) {
                uint32_t off = swz((uint32_t)((q0 + raA) * 128 + kk * 32 + caA));
                ldsm4(qfh[kk], sb + FSQ_H + off);
                ldsm4(qfl[kk], sb + FSQ_L + off);
            }
            qloaded = true;
        }

        uint32_t kvb = sb + FSKV + (uint32_t)(jb & 1) * FKV_STAGE;

        float s[8][4];
        #pragma unroll
        for (int j = 0; j < 8; j++)
            #pragma unroll
            for (int r = 0; r < 4; r++) s[j][r] = 0.f;

        #pragma unroll
        for (int kk = 0; kk < 4; kk++) {
            #pragma unroll
            for (int jp = 0; jp < 4; jp++) {
                uint32_t kh4[4], kl4[4];
                uint32_t off = swz((uint32_t)((jp * 16 + rbB) * 128 + kk * 32 + cbB));
                ldsm4(kh4, kvb + 0    + off);
                ldsm4(kl4, kvb + 8192 + off);
                #pragma unroll
                for (int hf = 0; hf < 2; hf++) {
                    int nt = jp * 2 + hf;
                    const uint32_t* Bh_ = &kh4[hf * 2];
                    const uint32_t* Bl_ = &kl4[hf * 2];
                    mma16816(s[nt], qfh[kk], Bh_);
                    mma16816(s[nt], qfh[kk], Bl_);
                    mma16816(s[nt], qfl[kk], Bh_);
                }
            }
        }

        int kv0 = jb * 64;
        #pragma unroll
        for (int nt = 0; nt < 8; nt++)
            #pragma unroll
            for (int r = 0; r < 4; r++) s[nt][r] *= SCALE;
        if (kv0 + 63 > grow0) {
            #pragma unroll
            for (int nt = 0; nt < 8; nt++) {
                int c = kv0 + nt * 8 + (lane & 3) * 2;
                if (c > grow0)     s[nt][0] = -1e30f;
                if (c + 1 > grow0) s[nt][1] = -1e30f;
                if (c > grow1)     s[nt][2] = -1e30f;
                if (c + 1 > grow1) s[nt][3] = -1e30f;
            }
        }

        float mxa = -1e30f, mxb = -1e30f;
        #pragma unroll
        for (int nt = 0; nt < 8; nt++) {
            mxa = fmaxf(mxa, fmaxf(s[nt][0], s[nt][1]));
            mxb = fmaxf(mxb, fmaxf(s[nt][2], s[nt][3]));
        }
        mxa = fmaxf(mxa, __shfl_xor_sync(0xffffffff, mxa, 1));
        mxa = fmaxf(mxa, __shfl_xor_sync(0xffffffff, mxa, 2));
        mxb = fmaxf(mxb, __shfl_xor_sync(0xffffffff, mxb, 1));
        mxb = fmaxf(mxb, __shfl_xor_sync(0xffffffff, mxb, 2));
        float mn0 = fmaxf(m0, mxa);
        float mn1 = fmaxf(m1, mxb);
        float al0 = __expf(m0 - mn0);
        float al1 = __expf(m1 - mn1);
        m0 = mn0; m1 = mn1;

        float p[8][4];
        float sum0 = 0.f, sum1 = 0.f;
        #pragma unroll
        for (int nt = 0; nt < 8; nt++) {
            p[nt][0] = __expf(s[nt][0] - mn0);
            p[nt][1] = __expf(s[nt][1] - mn0);
            p[nt][2] = __expf(s[nt][2] - mn1);
            p[nt][3] = __expf(s[nt][3] - mn1);
            sum0 += p[nt][0] + p[nt][1];
            sum1 += p[nt][2] + p[nt][3];
        }
        sum0 += __shfl_xor_sync(0xffffffff, sum0, 1);
        sum0 += __shfl_xor_sync(0xffffffff, sum0, 2);
        sum1 += __shfl_xor_sync(0xffffffff, sum1, 1);
        sum1 += __shfl_xor_sync(0xffffffff, sum1, 2);
        l0 = l0 * al0 + sum0;
        l1 = l1 * al1 + sum1;

        #pragma unroll
        for (int nt = 0; nt < 8; nt++) {
            o[nt][0] *= al0; o[nt][1] *= al0;
            o[nt][2] *= al1; o[nt][3] *= al1;
        }

        // ---- pack P as single fp16 A-frags ----
        uint32_t pfh[4][4];
        #pragma unroll
        for (int t = 0; t < 4; t++) {
            int n0 = 2 * t, n1 = 2 * t + 1;
            float e[8] = {p[n0][0], p[n0][1], p[n0][2], p[n0][3],
                          p[n1][0], p[n1][1], p[n1][2], p[n1][3]};
            #pragma unroll
            for (int g = 0; g < 4; g++) {
                __half2 hh = __floats2half2_rn(e[2*g], e[2*g+1]);
                pfh[t][g] = *(uint32_t*)&hh;
            }
        }

        // ---- O += P @ (Vh + Vl), 2 terms ----
        #pragma unroll
        for (int t = 0; t < 4; t++) {
            #pragma unroll
            for (int jp = 0; jp < 4; jp++) {
                uint32_t vh4[4], vl4[4];
                uint32_t off = swz((uint32_t)((t * 16 + vrow) * 128 + jp * 32 + vcol));
                ldsm4t(vh4, kvb + 16384 + off);
                ldsm4t(vl4, kvb + 24576 + off);
                #pragma unroll
                for (int hf = 0; hf < 2; hf++) {
                    int nt = jp * 2 + hf;
                    const uint32_t* Bh_ = &vh4[hf * 2];
                    const uint32_t* Bl_ = &vl4[hf * 2];
                    mma16816(o[nt], pfh[t], Bh_);
                    mma16816(o[nt], pfh[t], Bl_);
                }
            }
        }
        __syncthreads();
    }

    float inv0 = 1.f / l0;
    float inv1 = 1.f / l1;
    size_t r0g = (size_t)(b * SEQ + grow0) * DMODEL + h * DHEAD;
    size_t r1g = (size_t)(b * SEQ + grow1) * DMODEL + h * DHEAD;
    #pragma unroll
    for (int nt = 0; nt < 8; nt++) {
        int c = nt * 8 + (lane & 3) * 2;
        float v0 = o[nt][0] * inv0, v1 = o[nt][1] * inv0;
        float v2 = o[nt][2] * inv1, v3 = o[nt][3] * inv1;
        __half2 h01 = __floats2half2_rn(v0, v1);
        __half2 l01 = __floats2half2_rn(
            v0 - __half2float(h01.x), v1 - __half2float(h01.y));
        __half2 h23 = __floats2half2_rn(v2, v3);
        __half2 l23 = __floats2half2_rn(
            v2 - __half2float(h23.x), v3 - __half2float(h23.y));
        *(__half2*)(g_ah + r0g + c) = h01;
        *(__half2*)(g_al + r0g + c) = l01;
        *(__half2*)(g_ah + r1g + c) = h23;
        *(__half2*)(g_al + r1g + c) = l23;
    }
}

// ---------------- launch ----------------
extern "C" void kernel_launch(void* const* d_in, const int* in_sizes, int n_in,
                              void* d_out, int out_size)
{
    const float* x  = (const float*)d_in[0];
    const float* Wq = (const float*)d_in[1];
    const float* bq = (const float*)d_in[2];
    const float* Wk = (const float*)d_in[3];
    const float* bk = (const float*)d_in[4];
    const float* Wv = (const float*)d_in[5];
    const float* bv = (const float*)d_in[6];
    const float* Wo = (const float*)d_in[7];
    const float* bo = (const float*)d_in[8];
    float* out = (float*)d_out;

    __half *pah, *pal, *pqh, *pql, *pkh, *pkl, *pvh, *pvl;
    cudaGetSymbolAddress((void**)&pah, g_ah);
    cudaGetSymbolAddress((void**)&pal, g_al);
    cudaGetSymbolAddress((void**)&pqh, g_qh);
    cudaGetSymbolAddress((void**)&pql, g_ql);
    cudaGetSymbolAddress((void**)&pkh, g_kh);
    cudaGetSymbolAddress((void**)&pkl, g_kl);
    cudaGetSymbolAddress((void**)&pvh, g_vh);
    cudaGetSymbolAddress((void**)&pvl, g_vl);

    cudaFuncSetAttribute(gemm_big_kernel<1>,
                         cudaFuncAttributeMaxDynamicSharedMemorySize, SM_GEMM_TOTAL);
    cudaFuncSetAttribute(gemm_big_kernel<0>,
                         cudaFuncAttributeMaxDynamicSharedMemorySize, SM_GEMM_TOTAL);
    cudaFuncSetAttribute(flash_mma_kernel,
                         cudaFuncAttributeMaxDynamicSharedMemorySize, SM_FLASH_TOTAL);

    const int nA = MROWS * DMODEL;

    rope_table_kernel<<<SEQ, 32>>>();
    split_kernel<<<nA / 1024, 256>>>(x, pah, pal, nA);
    tsplit4_kernel<<<dim3(32, 32, 4), dim3(32, 8)>>>(Wq, Wk, Wv, Wo);

    // fused Q,K,V projections (2 CTAs/SM, 3-stage pipeline, 2-term fp16)
    gemm_big_kernel<1><<<dim3(8, 32, 3), 256, SM_GEMM_TOTAL>>>(
        pah, pal, bq, bk, bv,
        pqh, pql, pkh, pkl, pvh, pvl, nullptr);

    // attention: 64-row q tiles, 128 threads, 2 CTAs/SM, QK 3-term, PV 2-term
    flash_mma_kernel<<<dim3(SEQ / 64, BATCH * NHEADS), 128, SM_FLASH_TOTAL>>>();

    // O projection (weight slot 3, fp32 out)
    gemm_big_kernel<0><<<dim3(8, 32, 1), 256, SM_GEMM_TOTAL>>>(
        pah, pal, bo, nullptr, nullptr,
        nullptr, nullptr, nullptr, nullptr, nullptr, nullptr, out);
}